// round 10
// baseline (speedup 1.0000x reference)
#include <cuda_runtime.h>
#include <cuda_fp16.h>
#include <math.h>
#include <stdint.h>

#define SEQ 2048
#define DIM 4096
#define NH  32
#define HD  128
#define GK  8192    // A-side 2-segment fp16 K-concat: A=[hi|lo]; B = W_hi read twice

// ---------------- scratch (__device__ globals; no cudaMalloc allowed) -------
__device__ __half g_wh[4ull * DIM * DIM];                // weights hi, single copy
__device__ __half g_xsplit[(size_t)SEQ * GK];            // x        [hi|lo]
__device__ __half g_asplit[(size_t)SEQ * GK];            // attn out [hi|lo]
__device__ __half g_qs[(size_t)SEQ * NH * 256];          // q per head [hi128|lo128]
__device__ __half g_ks[(size_t)SEQ * NH * 128];          // k per head, plain fp16
__device__ __half g_vs[(size_t)SEQ * NH * 128];          // v per head, plain fp16

// ---------------- PTX helpers ----------------------------------------------
__device__ __forceinline__ uint32_t smem_u32(const void* p) {
    uint32_t a;
    asm("{ .reg .u64 t; cvta.to.shared.u64 t, %1; cvt.u32.u64 %0, t; }" : "=r"(a) : "l"(p));
    return a;
}
__device__ __forceinline__ void cp_async16(uint32_t dst, const void* src) {
    asm volatile("cp.async.cg.shared.global [%0], [%1], 16;" :: "r"(dst), "l"(src));
}
#define CP_COMMIT()  asm volatile("cp.async.commit_group;" ::: "memory")
#define CP_WAIT(n)   asm volatile("cp.async.wait_group %0;" :: "n"(n) : "memory")

__device__ __forceinline__ void ldm_x4(uint32_t* r, uint32_t addr) {
    asm volatile("ldmatrix.sync.aligned.m8n8.x4.shared.b16 {%0,%1,%2,%3}, [%4];"
        : "=r"(r[0]), "=r"(r[1]), "=r"(r[2]), "=r"(r[3]) : "r"(addr));
}
__device__ __forceinline__ void ldm_x4_t(uint32_t* r, uint32_t addr) {
    asm volatile("ldmatrix.sync.aligned.m8n8.x4.trans.shared.b16 {%0,%1,%2,%3}, [%4];"
        : "=r"(r[0]), "=r"(r[1]), "=r"(r[2]), "=r"(r[3]) : "r"(addr));
}
// fp16 mma, fp32 accum
__device__ __forceinline__ void mma16816h(float* c, const uint32_t* a, uint32_t b0, uint32_t b1) {
    asm volatile(
        "mma.sync.aligned.m16n8k16.row.col.f32.f16.f16.f32 "
        "{%0,%1,%2,%3}, {%4,%5,%6,%7}, {%8,%9}, {%0,%1,%2,%3};"
        : "+f"(c[0]), "+f"(c[1]), "+f"(c[2]), "+f"(c[3])
        : "r"(a[0]), "r"(a[1]), "r"(a[2]), "r"(a[3]), "r"(b0), "r"(b1));
}
// fp16 mma, fp16 accum (2x rate) — for small compensation terms
__device__ __forceinline__ void mma16816hh(uint32_t* c, const uint32_t* a, uint32_t b0, uint32_t b1) {
    asm volatile(
        "mma.sync.aligned.m16n8k16.row.col.f16.f16.f16.f16 "
        "{%0,%1}, {%2,%3,%4,%5}, {%6,%7}, {%0,%1};"
        : "+r"(c[0]), "+r"(c[1])
        : "r"(a[0]), "r"(a[1]), "r"(a[2]), "r"(a[3]), "r"(b0), "r"(b1));
}
__device__ __forceinline__ uint32_t packh2(float lo, float hi) {
    __half2 h = __floats2half2_rn(lo, hi);
    return *reinterpret_cast<uint32_t*>(&h);
}
__device__ __forceinline__ float h2_low(uint32_t r)  { return __low2float(*reinterpret_cast<__half2*>(&r)); }
__device__ __forceinline__ float h2_high(uint32_t r) { return __high2float(*reinterpret_cast<__half2*>(&r)); }

// ---------------- fp32 -> fp16 hi/lo split converters -----------------------
__device__ __forceinline__ void split4h(const float4 v, __half* hi, __half* lo) {
    float f[4] = {v.x, v.y, v.z, v.w};
#pragma unroll
    for (int i = 0; i < 4; i++) {
        hi[i] = __float2half_rn(f[i]);
        lo[i] = __float2half_rn(f[i] - __half2float(hi[i]));
    }
}

// Weights: single hi copy [DIM x DIM]
__global__ __launch_bounds__(256) void convert_w_kernel(
    const float* __restrict__ w0, const float* __restrict__ w1,
    const float* __restrict__ w2, const float* __restrict__ w3)
{
    const float* w = (blockIdx.z == 0) ? w0 : (blockIdx.z == 1) ? w1 :
                     (blockIdx.z == 2) ? w2 : w3;
    __half* dst = g_wh + (size_t)blockIdx.z * DIM * DIM;
    int idx = blockIdx.x * 256 + threadIdx.x;
    float4 v = reinterpret_cast<const float4*>(w)[idx];
    __half hi[4];
    hi[0] = __float2half_rn(v.x); hi[1] = __float2half_rn(v.y);
    hi[2] = __float2half_rn(v.z); hi[3] = __float2half_rn(v.w);
    *reinterpret_cast<uint2*>(dst + (size_t)idx * 4) = *reinterpret_cast<uint2*>(hi);
}

// x: [hi | lo]
__global__ __launch_bounds__(256) void convert_x_kernel(const float* __restrict__ x)
{
    int idx = blockIdx.x * 256 + threadIdx.x;
    int row = idx >> 10;
    int c4  = (idx & 1023) << 2;
    __half hi[4], lo[4];
    split4h(reinterpret_cast<const float4*>(x)[idx], hi, lo);
    size_t base = (size_t)row * GK + c4;
    *reinterpret_cast<uint2*>(g_xsplit + base)       = *reinterpret_cast<uint2*>(hi);
    *reinterpret_cast<uint2*>(g_xsplit + base + DIM) = *reinterpret_cast<uint2*>(lo);
}

// ---------------- HMMA fp16 GEMM, two-phase (lo f16-accum, hi f32-accum) ----
// C[128x128] = x_hi.W^T (f32 accum) + x_lo.W^T (f16 accum, unpacked at boundary)
// 256 threads, 8 warps (4m x 2n), warp tile 32x64, BK=32, 3-stage cp.async.
#define BK 32
#define NKSTEP (GK / BK)     // 256 (128 lo + 128 hi)
#define HALFK (NKSTEP / 2)   // 128
#define ASTR 40
#define GSTAGES 3
#define GEMM_SMEM (GSTAGES * 2 * 128 * ASTR * (int)sizeof(__half))  // 61440

__device__ __forceinline__ void hgemm_body(
    const __half* __restrict__ A,
    const __half* __restrict__ B,          // [4096 x 4096] hi
    float* __restrict__ C,                 // omode 0
    __half* __restrict__ hdst,             // omode 1 (q split) / 2 (plain kv)
    int omode,
    const float* __restrict__ freqs, int rope, float qsc,
    int m0, int n0)
{
    extern __shared__ __half gsm[];
    __half* sA = gsm;                          // GSTAGES x 128 x ASTR
    __half* sB = gsm + GSTAGES * 128 * ASTR;   // GSTAGES x 128 x ASTR

    const int tid  = threadIdx.x;
    const int wid  = tid >> 5;
    const int lane = tid & 31;
    const int wm   = wid >> 1;   // 0..3 -> rows wm*32
    const int wn   = wid & 1;    // 0..1 -> cols wn*64

    float acc[2][8][4];          // f32 accum (phase 2); initialized at boundary
    uint32_t acch[2][8][2];      // f16 accum (phase 1, lo terms)
#pragma unroll
    for (int mi = 0; mi < 2; mi++)
#pragma unroll
        for (int ni = 0; ni < 8; ni++) { acch[mi][ni][0] = 0u; acch[mi][ni][1] = 0u; }

    const __half* agp = A + (size_t)m0 * GK;
    const __half* bgp = B + (size_t)n0 * DIM;

    const int r0c = tid >> 2, seg0 = (tid & 3);
    const int r1c = (tid + 256) >> 2, seg1 = ((tid + 256) & 3);

    // k 0..127 -> lo segment (A offset DIM), k 128..255 -> hi segment
    auto load_tile = [&](int kstep, int s) {
        const size_t ka = (kstep < HALFK) ? (size_t)DIM + (size_t)kstep * BK
                                          : (size_t)(kstep - HALFK) * BK;
        const size_t kb = (size_t)(kstep & (HALFK - 1)) * BK;
        cp_async16(smem_u32(sA + (s * 128 + r0c) * ASTR + seg0 * 8), agp + (size_t)r0c * GK  + ka + seg0 * 8);
        cp_async16(smem_u32(sB + (s * 128 + r0c) * ASTR + seg0 * 8), bgp + (size_t)r0c * DIM + kb + seg0 * 8);
        cp_async16(smem_u32(sA + (s * 128 + r1c) * ASTR + seg1 * 8), agp + (size_t)r1c * GK  + ka + seg1 * 8);
        cp_async16(smem_u32(sB + (s * 128 + r1c) * ASTR + seg1 * 8), bgp + (size_t)r1c * DIM + kb + seg1 * 8);
        CP_COMMIT();
    };

    load_tile(0, 0);
    load_tile(1, 1);

    for (int k = 0; k < NKSTEP; k++) {
        if (k + 1 < NKSTEP) { CP_WAIT(1); } else { CP_WAIT(0); }
        __syncthreads();
        if (k + 2 < NKSTEP) load_tile(k + 2, (k + 2) % GSTAGES);

        if (k == HALFK) {
            // boundary: unpack f16 lo-accum into f32 acc
#pragma unroll
            for (int mi = 0; mi < 2; mi++)
#pragma unroll
                for (int ni = 0; ni < 8; ni++) {
                    acc[mi][ni][0] = h2_low(acch[mi][ni][0]);
                    acc[mi][ni][1] = h2_high(acch[mi][ni][0]);
                    acc[mi][ni][2] = h2_low(acch[mi][ni][1]);
                    acc[mi][ni][3] = h2_high(acch[mi][ni][1]);
                }
        }

        const int s = k % GSTAGES;
#pragma unroll
        for (int kk = 0; kk < 2; kk++) {
            const int k0 = kk * 16;
            uint32_t af[2][4], bf[8][2];
#pragma unroll
            for (int mi = 0; mi < 2; mi++) {
                int row = wm * 32 + mi * 16 + (lane & 15);
                ldm_x4(af[mi], smem_u32(sA + (s * 128 + row) * ASTR + k0 + ((lane >> 4) << 3)));
            }
#pragma unroll
            for (int np = 0; np < 4; np++) {
                int rown = wn * 64 + np * 16 + ((lane >> 4) << 3) + (lane & 7);
                uint32_t b[4];
                ldm_x4(b, smem_u32(sB + (s * 128 + rown) * ASTR + k0 + (((lane >> 3) & 1) << 3)));
                bf[2 * np][0] = b[0];  bf[2 * np][1] = b[1];
                bf[2 * np + 1][0] = b[2];  bf[2 * np + 1][1] = b[3];
            }
            if (k < HALFK) {
#pragma unroll
                for (int mi = 0; mi < 2; mi++)
#pragma unroll
                    for (int ni = 0; ni < 8; ni++)
                        mma16816hh(acch[mi][ni], af[mi], bf[ni][0], bf[ni][1]);
            } else {
#pragma unroll
                for (int mi = 0; mi < 2; mi++)
#pragma unroll
                    for (int ni = 0; ni < 8; ni++)
                        mma16816h(acc[mi][ni], af[mi], bf[ni][0], bf[ni][1]);
            }
        }
    }

#pragma unroll
    for (int mi = 0; mi < 2; mi++) {
        const int ra = m0 + wm * 32 + mi * 16 + (lane >> 2);
        const int rb = ra + 8;
#pragma unroll
        for (int ni = 0; ni < 8; ni++) {
            const int col = n0 + wn * 64 + ni * 8 + ((lane & 3) << 1);
            float d0 = acc[mi][ni][0], d1 = acc[mi][ni][1];
            float d2 = acc[mi][ni][2], d3 = acc[mi][ni][3];
            if (rope) {
                const int hd = col & (HD - 1);          // even
                float ca = freqs[ra * HD + hd], sa = freqs[ra * HD + hd + 1];
                float cb = freqs[rb * HD + hd], sb = freqs[rb * HD + hd + 1];
                d0 *= (ca - sa) * qsc;  d1 *= (ca + sa) * qsc;
                d2 *= (cb - sb) * qsc;  d3 *= (cb + sb) * qsc;
            }
            if (omode == 1) {                       // q: split [hi|lo]
                const int head = col >> 7, d = col & 127;
                __half* pa = hdst + ((size_t)ra * NH + head) * 256 + d;
                uint32_t hi = packh2(d0, d1);
                uint32_t lo = packh2(d0 - h2_low(hi), d1 - h2_high(hi));
                *reinterpret_cast<uint32_t*>(pa)       = hi;
                *reinterpret_cast<uint32_t*>(pa + 128) = lo;
                __half* pb = hdst + ((size_t)rb * NH + head) * 256 + d;
                hi = packh2(d2, d3);
                lo = packh2(d2 - h2_low(hi), d3 - h2_high(hi));
                *reinterpret_cast<uint32_t*>(pb)       = hi;
                *reinterpret_cast<uint32_t*>(pb + 128) = lo;
            } else if (omode == 2) {                // k/v: plain fp16
                const int head = col >> 7, d = col & 127;
                *reinterpret_cast<uint32_t*>(hdst + ((size_t)ra * NH + head) * 128 + d) = packh2(d0, d1);
                *reinterpret_cast<uint32_t*>(hdst + ((size_t)rb * NH + head) * 128 + d) = packh2(d2, d3);
            } else {
                *reinterpret_cast<float2*>(&C[(size_t)ra * DIM + col]) = make_float2(d0, d1);
                *reinterpret_cast<float2*>(&C[(size_t)rb * DIM + col]) = make_float2(d2, d3);
            }
        }
    }
}

__global__ __launch_bounds__(256, 2) void qkv_gemm_kernel(const float* __restrict__ freqs)
{
    const int z = blockIdx.z;
    const __half* B = g_wh + (size_t)z * DIM * DIM;
    __half* dst = (z == 0) ? g_qs : (z == 1) ? g_ks : g_vs;
    const float qsc = (z == 0) ? 0.08838834764831845f : 1.0f;
    hgemm_body(g_xsplit, B, nullptr, dst, (z == 0) ? 1 : 2, freqs, (z < 2) ? 1 : 0, qsc,
               blockIdx.x * 128, blockIdx.y * 128);
}

__global__ __launch_bounds__(256, 2) void out_gemm_kernel(float* __restrict__ out)
{
    hgemm_body(g_asplit, g_wh + 3ull * DIM * DIM, out, nullptr, 0, nullptr, 0, 1.0f,
               blockIdx.x * 128, blockIdx.y * 128);
}

// ---------------- fp16 flash attention (lo terms f16-accum) -----------------
// CTA: 128 q x 64 kv, 8 warps. q split [hi|lo]; K,V plain fp16.
// S = q_hi.K (f32) + q_lo.K (f16) ; O += P_hi.V (f32) + P_lo.V (f16, per tile)
#define AQS 264                       // q smem row stride (256 + 8)
#define KVS 136                       // k/v smem row stride (128 + 8)
#define ATTN_SMEM ((128 * AQS + 4 * 64 * KVS) * (int)sizeof(__half))

__global__ __launch_bounds__(256, 1) void attn_kernel()
{
    extern __shared__ __half sm_attn[];
    __half* sQ = sm_attn;                  // 128 x AQS
    __half* sK = sQ + 128 * AQS;           // 2 x 64 x KVS
    __half* sV = sK + 2 * 64 * KVS;        // 2 x 64 x KVS

    const int h   = blockIdx.y;
    const int q0  = blockIdx.x * 128;
    const int tid = threadIdx.x;
    const int wid = tid >> 5, lane = tid & 31;

    for (int i = tid; i < 128 * 32; i += 256) {
        int r = i >> 5, c = i & 31;
        cp_async16(smem_u32(sQ + r * AQS) + c * 16,
                   g_qs + ((size_t)(q0 + r) * NH + h) * 256 + c * 8);
    }
    CP_COMMIT();

    const int nt = q0 / 64 + 2;

    auto load_kv = [&](int t, int s) {
        for (int i = tid; i < 64 * 16 * 2; i += 256) {
            int half_sel = i >= 64 * 16;
            int j = i & (64 * 16 - 1);
            int r = j >> 4, c = j & 15;
            size_t src = ((size_t)(t * 64 + r) * NH + h) * 128 + c * 8;
            __half* dst = (half_sel ? sV : sK) + (s * 64 + r) * KVS + c * 8;
            cp_async16(smem_u32(dst), (half_sel ? g_vs : g_ks) + src);
        }
        CP_COMMIT();
    };
    load_kv(0, 0);

    float m0 = -1e30f, m1 = -1e30f, l0 = 0.0f, l1 = 0.0f;
    float O[16][4];
#pragma unroll
    for (int n = 0; n < 16; n++)
#pragma unroll
        for (int j = 0; j < 4; j++) O[n][j] = 0.0f;

    const int wrow = q0 + wid * 16;
    const int r0g  = wrow + (lane >> 2);
    const uint32_t Qb = smem_u32(sQ);
    const uint32_t qrow_off = (uint32_t)((wid * 16 + (lane & 15)) * AQS + ((lane >> 4) << 3));
    const uint32_t krow = (uint32_t)(((lane >> 4) << 3) + (lane & 7));
    const uint32_t kcol = (uint32_t)(((lane >> 3) & 1) << 3);
    const uint32_t vrow_off = (uint32_t)(lane & 15);
    const uint32_t vcol8 = (uint32_t)((lane >> 4) << 3);

    for (int t = 0; t < nt; t++) {
        if (t + 1 < nt) { load_kv(t + 1, (t + 1) & 1); CP_WAIT(1); }
        else           { CP_WAIT(0); }
        __syncthreads();
        const int k0 = t * 64;

        if (k0 <= wrow + 15) {
            const uint32_t Kb = smem_u32(sK + (t & 1) * 64 * KVS);
            const uint32_t Vb = smem_u32(sV + (t & 1) * 64 * KVS);

            float s[8][4];
            uint32_t sl[8][2];
#pragma unroll
            for (int j = 0; j < 8; j++) {
#pragma unroll
                for (int i = 0; i < 4; i++) s[j][i] = 0.0f;
                sl[j][0] = 0u; sl[j][1] = 0u;
            }

            // ---- S = q_hi.K (f32) + q_lo.K (f16 accum) ----
#pragma unroll
            for (int kk = 0; kk < 8; kk++) {
                uint32_t qh[4], ql[4];
                ldm_x4(qh, Qb + (qrow_off + kk * 16) * 2);
                ldm_x4(ql, Qb + (qrow_off + 128 + kk * 16) * 2);
#pragma unroll
                for (int g = 0; g < 4; g++) {
                    uint32_t kb[4];
                    ldm_x4(kb, Kb + ((g * 16 + krow) * KVS + kcol + kk * 16) * 2);
                    mma16816h(s[2 * g],      qh, kb[0], kb[1]);
                    mma16816h(s[2 * g + 1],  qh, kb[2], kb[3]);
                    mma16816hh(sl[2 * g],     ql, kb[0], kb[1]);
                    mma16816hh(sl[2 * g + 1], ql, kb[2], kb[3]);
                }
            }
            // merge lo into f32 scores
#pragma unroll
            for (int j = 0; j < 8; j++) {
                s[j][0] += h2_low(sl[j][0]);
                s[j][1] += h2_high(sl[j][0]);
                s[j][2] += h2_low(sl[j][1]);
                s[j][3] += h2_high(sl[j][1]);
            }

            if (k0 + 63 > wrow) {
                const int c0 = k0 + ((lane & 3) << 1);
#pragma unroll
                for (int j = 0; j < 8; j++) {
                    int cc = c0 + j * 8;
                    if (cc     > r0g)     s[j][0] = -1e30f;
                    if (cc + 1 > r0g)     s[j][1] = -1e30f;
                    if (cc     > r0g + 8) s[j][2] = -1e30f;
                    if (cc + 1 > r0g + 8) s[j][3] = -1e30f;
                }
            }

            float mt0 = -1e30f, mt1 = -1e30f;
#pragma unroll
            for (int j = 0; j < 8; j++) {
                mt0 = fmaxf(mt0, fmaxf(s[j][0], s[j][1]));
                mt1 = fmaxf(mt1, fmaxf(s[j][2], s[j][3]));
            }
            mt0 = fmaxf(mt0, __shfl_xor_sync(0xffffffffu, mt0, 1));
            mt0 = fmaxf(mt0, __shfl_xor_sync(0xffffffffu, mt0, 2));
            mt1 = fmaxf(mt1, __shfl_xor_sync(0xffffffffu, mt1, 1));
            mt1 = fmaxf(mt1, __shfl_xor_sync(0xffffffffu, mt1, 2));
            const float mn0 = fmaxf(m0, mt0), mn1 = fmaxf(m1, mt1);
            const float corr0 = __expf(m0 - mn0), corr1 = __expf(m1 - mn1);
            m0 = mn0; m1 = mn1;
            float rs0 = 0.0f, rs1 = 0.0f;
#pragma unroll
            for (int j = 0; j < 8; j++) {
                s[j][0] = __expf(s[j][0] - mn0);
                s[j][1] = __expf(s[j][1] - mn0);
                s[j][2] = __expf(s[j][2] - mn1);
                s[j][3] = __expf(s[j][3] - mn1);
                rs0 += s[j][0] + s[j][1];
                rs1 += s[j][2] + s[j][3];
            }
            rs0 += __shfl_xor_sync(0xffffffffu, rs0, 1);
            rs0 += __shfl_xor_sync(0xffffffffu, rs0, 2);
            rs1 += __shfl_xor_sync(0xffffffffu, rs1, 1);
            rs1 += __shfl_xor_sync(0xffffffffu, rs1, 2);
            l0 = l0 * corr0 + rs0;
            l1 = l1 * corr1 + rs1;
#pragma unroll
            for (int n = 0; n < 16; n++) {
                O[n][0] *= corr0;  O[n][1] *= corr0;
                O[n][2] *= corr1;  O[n][3] *= corr1;
            }

            // ---- O += P_hi.V (f32) + P_lo.V (f16 accum per tile) ----
            uint32_t Ol[16][2];
#pragma unroll
            for (int n = 0; n < 16; n++) { Ol[n][0] = 0u; Ol[n][1] = 0u; }
#pragma unroll
            for (int kt = 0; kt < 4; kt++) {
                uint32_t ph[4], pl[4];
                ph[0] = packh2(s[2 * kt][0], s[2 * kt][1]);
                pl[0] = packh2(s[2 * kt][0] - h2_low(ph[0]), s[2 * kt][1] - h2_high(ph[0]));
                ph[1] = packh2(s[2 * kt][2], s[2 * kt][3]);
                pl[1] = packh2(s[2 * kt][2] - h2_low(ph[1]), s[2 * kt][3] - h2_high(ph[1]));
                ph[2] = packh2(s[2 * kt + 1][0], s[2 * kt + 1][1]);
                pl[2] = packh2(s[2 * kt + 1][0] - h2_low(ph[2]), s[2 * kt + 1][1] - h2_high(ph[2]));
                ph[3] = packh2(s[2 * kt + 1][2], s[2 * kt + 1][3]);
                pl[3] = packh2(s[2 * kt + 1][2] - h2_low(ph[3]), s[2 * kt + 1][3] - h2_high(ph[3]));
#pragma unroll
                for (int g = 0; g < 8; g++) {
                    uint32_t vb[4];
                    ldm_x4_t(vb, Vb + ((kt * 16 + vrow_off) * KVS + g * 16 + vcol8) * 2);
                    mma16816h(O[2 * g],      ph, vb[0], vb[1]);
                    mma16816h(O[2 * g + 1],  ph, vb[2], vb[3]);
                    mma16816hh(Ol[2 * g],     pl, vb[0], vb[1]);
                    mma16816hh(Ol[2 * g + 1], pl, vb[2], vb[3]);
                }
            }
#pragma unroll
            for (int n = 0; n < 16; n++) {
                O[n][0] += h2_low(Ol[n][0]);
                O[n][1] += h2_high(Ol[n][0]);
                O[n][2] += h2_low(Ol[n][1]);
                O[n][3] += h2_high(Ol[n][1]);
            }
        }
        __syncthreads();
    }

    // ---- normalize + split-store to g_asplit [hi|lo] fp16 ----
    const float inv0 = 1.0f / l0, inv1 = 1.0f / l1;
    const int sr0 = wrow + (lane >> 2), sr1 = sr0 + 8;
#pragma unroll
    for (int n = 0; n < 16; n++) {
        const int d = n * 8 + ((lane & 3) << 1);
        {
            float v0 = O[n][0] * inv0, v1 = O[n][1] * inv0;
            uint32_t hi = packh2(v0, v1);
            uint32_t lo = packh2(v0 - h2_low(hi), v1 - h2_high(hi));
            __half* p = g_asplit + (size_t)sr0 * GK + h * 128 + d;
            *reinterpret_cast<uint32_t*>(p)       = hi;
            *reinterpret_cast<uint32_t*>(p + DIM) = lo;
        }
        {
            float v2 = O[n][2] * inv1, v3 = O[n][3] * inv1;
            uint32_t hi = packh2(v2, v3);
            uint32_t lo = packh2(v2 - h2_low(hi), v3 - h2_high(hi));
            __half* p = g_asplit + (size_t)sr1 * GK + h * 128 + d;
            *reinterpret_cast<uint32_t*>(p)       = hi;
            *reinterpret_cast<uint32_t*>(p + DIM) = lo;
        }
    }
}

// ---------------- launch -----------------------------------------------------
// inputs: 0:x 1:start_pos 2:freqs 3:mask 4:wq 5:wk 6:wv 7:wo  (mask analytic)
extern "C" void kernel_launch(void* const* d_in, const int* in_sizes, int n_in,
                              void* d_out, int out_size)
{
    const float* x     = (const float*)d_in[0];
    const float* freqs = (const float*)d_in[2];
    const float* wq    = (const float*)d_in[4];
    const float* wk    = (const float*)d_in[5];
    const float* wv    = (const float*)d_in[6];
    const float* wo    = (const float*)d_in[7];
    float* out = (float*)d_out;

    cudaFuncSetAttribute(attn_kernel,     cudaFuncAttributeMaxDynamicSharedMemorySize, ATTN_SMEM);
    cudaFuncSetAttribute(qkv_gemm_kernel, cudaFuncAttributeMaxDynamicSharedMemorySize, GEMM_SMEM);
    cudaFuncSetAttribute(out_gemm_kernel, cudaFuncAttributeMaxDynamicSharedMemorySize, GEMM_SMEM);

    convert_w_kernel<<<dim3(DIM * DIM / 4 / 256, 1, 4), 256>>>(wq, wk, wv, wo);
    convert_x_kernel<<<SEQ * DIM / 4 / 256, 256>>>(x);
    qkv_gemm_kernel<<<dim3(SEQ / 128, DIM / 128, 3), 256, GEMM_SMEM>>>(freqs);
    attn_kernel<<<dim3(SEQ / 128, NH), 256, ATTN_SMEM>>>();
    out_gemm_kernel<<<dim3(SEQ / 128, DIM / 128, 1), 256, GEMM_SMEM>>>(out);
}

// round 11
// speedup vs baseline: 1.2290x; 1.2290x over previous
#include <cuda_runtime.h>
#include <cuda_fp16.h>
#include <math.h>
#include <stdint.h>

#define SEQ 2048
#define DIM 4096
#define NH  32
#define HD  128
#define GK  8192    // A-side 2-segment fp16 K-concat: A=[hi|lo]; B = W_hi read twice

// ---------------- scratch (__device__ globals; no cudaMalloc allowed) -------
__device__ __half g_wh[4ull * DIM * DIM];                // weights hi, single copy
__device__ __half g_xsplit[(size_t)SEQ * GK];            // x        [hi|lo]
__device__ __half g_asplit[(size_t)SEQ * GK];            // attn out [hi|lo]
__device__ __half g_qs[(size_t)SEQ * NH * 256];          // q per head [hi128|lo128]
__device__ __half g_ks[(size_t)SEQ * NH * 128];          // k per head, plain fp16
__device__ __half g_vs[(size_t)SEQ * NH * 128];          // v per head, plain fp16

// ---------------- PTX helpers ----------------------------------------------
__device__ __forceinline__ uint32_t smem_u32(const void* p) {
    uint32_t a;
    asm("{ .reg .u64 t; cvta.to.shared.u64 t, %1; cvt.u32.u64 %0, t; }" : "=r"(a) : "l"(p));
    return a;
}
__device__ __forceinline__ void cp_async16(uint32_t dst, const void* src) {
    asm volatile("cp.async.cg.shared.global [%0], [%1], 16;" :: "r"(dst), "l"(src));
}
#define CP_COMMIT()  asm volatile("cp.async.commit_group;" ::: "memory")
#define CP_WAIT(n)   asm volatile("cp.async.wait_group %0;" :: "n"(n) : "memory")

__device__ __forceinline__ void ldm_x4(uint32_t* r, uint32_t addr) {
    asm volatile("ldmatrix.sync.aligned.m8n8.x4.shared.b16 {%0,%1,%2,%3}, [%4];"
        : "=r"(r[0]), "=r"(r[1]), "=r"(r[2]), "=r"(r[3]) : "r"(addr));
}
__device__ __forceinline__ void ldm_x4_t(uint32_t* r, uint32_t addr) {
    asm volatile("ldmatrix.sync.aligned.m8n8.x4.trans.shared.b16 {%0,%1,%2,%3}, [%4];"
        : "=r"(r[0]), "=r"(r[1]), "=r"(r[2]), "=r"(r[3]) : "r"(addr));
}
// fp16 mma, fp32 accum
__device__ __forceinline__ void mma16816h(float* c, const uint32_t* a, uint32_t b0, uint32_t b1) {
    asm volatile(
        "mma.sync.aligned.m16n8k16.row.col.f32.f16.f16.f32 "
        "{%0,%1,%2,%3}, {%4,%5,%6,%7}, {%8,%9}, {%0,%1,%2,%3};"
        : "+f"(c[0]), "+f"(c[1]), "+f"(c[2]), "+f"(c[3])
        : "r"(a[0]), "r"(a[1]), "r"(a[2]), "r"(a[3]), "r"(b0), "r"(b1));
}
__device__ __forceinline__ uint32_t packh2(float lo, float hi) {
    __half2 h = __floats2half2_rn(lo, hi);
    return *reinterpret_cast<uint32_t*>(&h);
}
__device__ __forceinline__ float h2_low(uint32_t r)  { return __low2float(*reinterpret_cast<__half2*>(&r)); }
__device__ __forceinline__ float h2_high(uint32_t r) { return __high2float(*reinterpret_cast<__half2*>(&r)); }

// ---------------- fp32 -> fp16 hi/lo split converters -----------------------
__device__ __forceinline__ void split4h(const float4 v, __half* hi, __half* lo) {
    float f[4] = {v.x, v.y, v.z, v.w};
#pragma unroll
    for (int i = 0; i < 4; i++) {
        hi[i] = __float2half_rn(f[i]);
        lo[i] = __float2half_rn(f[i] - __half2float(hi[i]));
    }
}

// Weights: single hi copy [DIM x DIM]
__global__ __launch_bounds__(256) void convert_w_kernel(
    const float* __restrict__ w0, const float* __restrict__ w1,
    const float* __restrict__ w2, const float* __restrict__ w3)
{
    const float* w = (blockIdx.z == 0) ? w0 : (blockIdx.z == 1) ? w1 :
                     (blockIdx.z == 2) ? w2 : w3;
    __half* dst = g_wh + (size_t)blockIdx.z * DIM * DIM;
    int idx = blockIdx.x * 256 + threadIdx.x;
    float4 v = reinterpret_cast<const float4*>(w)[idx];
    __half hi[4];
    hi[0] = __float2half_rn(v.x); hi[1] = __float2half_rn(v.y);
    hi[2] = __float2half_rn(v.z); hi[3] = __float2half_rn(v.w);
    *reinterpret_cast<uint2*>(dst + (size_t)idx * 4) = *reinterpret_cast<uint2*>(hi);
}

// x: [hi | lo]
__global__ __launch_bounds__(256) void convert_x_kernel(const float* __restrict__ x)
{
    int idx = blockIdx.x * 256 + threadIdx.x;
    int row = idx >> 10;
    int c4  = (idx & 1023) << 2;
    __half hi[4], lo[4];
    split4h(reinterpret_cast<const float4*>(x)[idx], hi, lo);
    size_t base = (size_t)row * GK + c4;
    *reinterpret_cast<uint2*>(g_xsplit + base)       = *reinterpret_cast<uint2*>(hi);
    *reinterpret_cast<uint2*>(g_xsplit + base + DIM) = *reinterpret_cast<uint2*>(lo);
}

// ---------------- HMMA fp16 GEMM: 4 warps, warp tile 64x64 ------------------
// C[128x128] = A'[M,GK] . B'[N,GK]^T (B col k reads W_hi col k&4095).
// 128 threads, 4 warps (2m x 2n), warp tile 64x64, BK=32, 3-stage cp.async.
// bytes/MMA = 128 (vs 192 with 32x64 warps) -> crossbar relief.
#define BK 32
#define NKSTEP (GK / BK)     // 256
#define ASTR 40
#define GSTAGES 3
#define GEMM_SMEM (GSTAGES * 2 * 128 * ASTR * (int)sizeof(__half))  // 61440

__device__ __forceinline__ void hgemm_body(
    const __half* __restrict__ A,
    const __half* __restrict__ B,          // [4096 x 4096] hi
    float* __restrict__ C,                 // omode 0
    __half* __restrict__ hdst,             // omode 1 (q split) / 2 (plain kv)
    int omode,
    const float* __restrict__ freqs, int rope, float qsc,
    int m0, int n0)
{
    extern __shared__ __half gsm[];
    __half* sA = gsm;                          // GSTAGES x 128 x ASTR
    __half* sB = gsm + GSTAGES * 128 * ASTR;   // GSTAGES x 128 x ASTR

    const int tid  = threadIdx.x;
    const int wid  = tid >> 5;
    const int lane = tid & 31;
    const int wm   = wid >> 1;   // 0..1 -> rows wm*64
    const int wn   = wid & 1;    // 0..1 -> cols wn*64

    float acc[4][8][4];
#pragma unroll
    for (int mi = 0; mi < 4; mi++)
#pragma unroll
        for (int ni = 0; ni < 8; ni++)
#pragma unroll
            for (int j = 0; j < 4; j++) acc[mi][ni][j] = 0.0f;

    const __half* agp = A + (size_t)m0 * GK;
    const __half* bgp = B + (size_t)n0 * DIM;

    auto load_tile = [&](int kstep, int s) {
        const size_t ka = (size_t)kstep * BK;
        const size_t kb = ka & (DIM - 1);
        // A,B: 512 16B chunks each, 128 threads -> 4 each
#pragma unroll
        for (int l = 0; l < 4; l++) {
            int i = tid + l * 128;
            int r = i >> 2, seg = i & 3;
            cp_async16(smem_u32(sA + (s * 128 + r) * ASTR + seg * 8), agp + (size_t)r * GK  + ka + seg * 8);
            cp_async16(smem_u32(sB + (s * 128 + r) * ASTR + seg * 8), bgp + (size_t)r * DIM + kb + seg * 8);
        }
        CP_COMMIT();
    };

    load_tile(0, 0);
    load_tile(1, 1);

    for (int k = 0; k < NKSTEP; k++) {
        if (k + 1 < NKSTEP) { CP_WAIT(1); } else { CP_WAIT(0); }
        __syncthreads();
        if (k + 2 < NKSTEP) load_tile(k + 2, (k + 2) % GSTAGES);

        const int s = k % GSTAGES;
#pragma unroll
        for (int kk = 0; kk < 2; kk++) {
            const int k0 = kk * 16;
            uint32_t af[4][4], bf[8][2];
#pragma unroll
            for (int mi = 0; mi < 4; mi++) {
                int row = wm * 64 + mi * 16 + (lane & 15);
                ldm_x4(af[mi], smem_u32(sA + (s * 128 + row) * ASTR + k0 + ((lane >> 4) << 3)));
            }
#pragma unroll
            for (int np = 0; np < 4; np++) {
                int rown = wn * 64 + np * 16 + ((lane >> 4) << 3) + (lane & 7);
                uint32_t b[4];
                ldm_x4(b, smem_u32(sB + (s * 128 + rown) * ASTR + k0 + (((lane >> 3) & 1) << 3)));
                bf[2 * np][0] = b[0];  bf[2 * np][1] = b[1];
                bf[2 * np + 1][0] = b[2];  bf[2 * np + 1][1] = b[3];
            }
#pragma unroll
            for (int mi = 0; mi < 4; mi++)
#pragma unroll
                for (int ni = 0; ni < 8; ni++)
                    mma16816h(acc[mi][ni], af[mi], bf[ni][0], bf[ni][1]);
        }
    }

#pragma unroll
    for (int mi = 0; mi < 4; mi++) {
        const int ra = m0 + wm * 64 + mi * 16 + (lane >> 2);
        const int rb = ra + 8;
#pragma unroll
        for (int ni = 0; ni < 8; ni++) {
            const int col = n0 + wn * 64 + ni * 8 + ((lane & 3) << 1);
            float d0 = acc[mi][ni][0], d1 = acc[mi][ni][1];
            float d2 = acc[mi][ni][2], d3 = acc[mi][ni][3];
            if (rope) {
                const int hd = col & (HD - 1);          // even
                float ca = freqs[ra * HD + hd], sa = freqs[ra * HD + hd + 1];
                float cb = freqs[rb * HD + hd], sb = freqs[rb * HD + hd + 1];
                d0 *= (ca - sa) * qsc;  d1 *= (ca + sa) * qsc;
                d2 *= (cb - sb) * qsc;  d3 *= (cb + sb) * qsc;
            }
            if (omode == 1) {                       // q: split [hi|lo]
                const int head = col >> 7, d = col & 127;
                __half* pa = hdst + ((size_t)ra * NH + head) * 256 + d;
                uint32_t hi = packh2(d0, d1);
                uint32_t lo = packh2(d0 - h2_low(hi), d1 - h2_high(hi));
                *reinterpret_cast<uint32_t*>(pa)       = hi;
                *reinterpret_cast<uint32_t*>(pa + 128) = lo;
                __half* pb = hdst + ((size_t)rb * NH + head) * 256 + d;
                hi = packh2(d2, d3);
                lo = packh2(d2 - h2_low(hi), d3 - h2_high(hi));
                *reinterpret_cast<uint32_t*>(pb)       = hi;
                *reinterpret_cast<uint32_t*>(pb + 128) = lo;
            } else if (omode == 2) {                // k/v: plain fp16
                const int head = col >> 7, d = col & 127;
                *reinterpret_cast<uint32_t*>(hdst + ((size_t)ra * NH + head) * 128 + d) = packh2(d0, d1);
                *reinterpret_cast<uint32_t*>(hdst + ((size_t)rb * NH + head) * 128 + d) = packh2(d2, d3);
            } else {
                *reinterpret_cast<float2*>(&C[(size_t)ra * DIM + col]) = make_float2(d0, d1);
                *reinterpret_cast<float2*>(&C[(size_t)rb * DIM + col]) = make_float2(d2, d3);
            }
        }
    }
}

__global__ __launch_bounds__(128, 2) void qkv_gemm_kernel(const float* __restrict__ freqs)
{
    const int z = blockIdx.z;
    const __half* B = g_wh + (size_t)z * DIM * DIM;
    __half* dst = (z == 0) ? g_qs : (z == 1) ? g_ks : g_vs;
    const float qsc = (z == 0) ? 0.08838834764831845f : 1.0f;
    hgemm_body(g_xsplit, B, nullptr, dst, (z == 0) ? 1 : 2, freqs, (z < 2) ? 1 : 0, qsc,
               blockIdx.x * 128, blockIdx.y * 128);
}

__global__ __launch_bounds__(128, 2) void out_gemm_kernel(float* __restrict__ out)
{
    hgemm_body(g_asplit, g_wh + 3ull * DIM * DIM, out, nullptr, 0, nullptr, 0, 1.0f,
               blockIdx.x * 128, blockIdx.y * 128);
}

// ---------------- fp16 flash attention (R9, heavy-tiles-first) --------------
// CTA: 128 q x 64 kv, 8 warps. q split [hi|lo]; K,V plain fp16.
// S = q_hi.K + q_lo.K ; O += P_hi.V + P_lo.V
#define AQS 264                       // q smem row stride (256 + 8)
#define KVS 136                       // k/v smem row stride (128 + 8)
#define ATTN_SMEM ((128 * AQS + 4 * 64 * KVS) * (int)sizeof(__half))

__global__ __launch_bounds__(256, 1) void attn_kernel()
{
    extern __shared__ __half sm_attn[];
    __half* sQ = sm_attn;                  // 128 x AQS
    __half* sK = sQ + 128 * AQS;           // 2 x 64 x KVS
    __half* sV = sK + 2 * 64 * KVS;        // 2 x 64 x KVS

    const int h   = blockIdx.y;
    const int q0  = (gridDim.x - 1 - blockIdx.x) * 128;   // heavy tiles first
    const int tid = threadIdx.x;
    const int wid = tid >> 5, lane = tid & 31;

    for (int i = tid; i < 128 * 32; i += 256) {
        int r = i >> 5, c = i & 31;
        cp_async16(smem_u32(sQ + r * AQS) + c * 16,
                   g_qs + ((size_t)(q0 + r) * NH + h) * 256 + c * 8);
    }
    CP_COMMIT();

    const int nt = q0 / 64 + 2;

    auto load_kv = [&](int t, int s) {
        for (int i = tid; i < 64 * 16 * 2; i += 256) {
            int half_sel = i >= 64 * 16;
            int j = i & (64 * 16 - 1);
            int r = j >> 4, c = j & 15;
            size_t src = ((size_t)(t * 64 + r) * NH + h) * 128 + c * 8;
            __half* dst = (half_sel ? sV : sK) + (s * 64 + r) * KVS + c * 8;
            cp_async16(smem_u32(dst), (half_sel ? g_vs : g_ks) + src);
        }
        CP_COMMIT();
    };
    load_kv(0, 0);

    float m0 = -1e30f, m1 = -1e30f, l0 = 0.0f, l1 = 0.0f;
    float O[16][4];
#pragma unroll
    for (int n = 0; n < 16; n++)
#pragma unroll
        for (int j = 0; j < 4; j++) O[n][j] = 0.0f;

    const int wrow = q0 + wid * 16;
    const int r0g  = wrow + (lane >> 2);
    const uint32_t Qb = smem_u32(sQ);
    const uint32_t qrow_off = (uint32_t)((wid * 16 + (lane & 15)) * AQS + ((lane >> 4) << 3));
    const uint32_t krow = (uint32_t)(((lane >> 4) << 3) + (lane & 7));
    const uint32_t kcol = (uint32_t)(((lane >> 3) & 1) << 3);
    const uint32_t vrow_off = (uint32_t)(lane & 15);
    const uint32_t vcol8 = (uint32_t)((lane >> 4) << 3);

    for (int t = 0; t < nt; t++) {
        if (t + 1 < nt) { load_kv(t + 1, (t + 1) & 1); CP_WAIT(1); }
        else           { CP_WAIT(0); }
        __syncthreads();
        const int k0 = t * 64;

        if (k0 <= wrow + 15) {
            const uint32_t Kb = smem_u32(sK + (t & 1) * 64 * KVS);
            const uint32_t Vb = smem_u32(sV + (t & 1) * 64 * KVS);

            float s[8][4];
#pragma unroll
            for (int j = 0; j < 8; j++)
#pragma unroll
                for (int i = 0; i < 4; i++) s[j][i] = 0.0f;

            // ---- S = (q_hi + q_lo) . K ----
#pragma unroll
            for (int kk = 0; kk < 8; kk++) {
                uint32_t qh[4], ql[4];
                ldm_x4(qh, Qb + (qrow_off + kk * 16) * 2);
                ldm_x4(ql, Qb + (qrow_off + 128 + kk * 16) * 2);
#pragma unroll
                for (int g = 0; g < 4; g++) {
                    uint32_t kb[4];
                    ldm_x4(kb, Kb + ((g * 16 + krow) * KVS + kcol + kk * 16) * 2);
                    mma16816h(s[2 * g],     qh, kb[0], kb[1]);
                    mma16816h(s[2 * g + 1], qh, kb[2], kb[3]);
                    mma16816h(s[2 * g],     ql, kb[0], kb[1]);
                    mma16816h(s[2 * g + 1], ql, kb[2], kb[3]);
                }
            }

            if (k0 + 63 > wrow) {
                const int c0 = k0 + ((lane & 3) << 1);
#pragma unroll
                for (int j = 0; j < 8; j++) {
                    int cc = c0 + j * 8;
                    if (cc     > r0g)     s[j][0] = -1e30f;
                    if (cc + 1 > r0g)     s[j][1] = -1e30f;
                    if (cc     > r0g + 8) s[j][2] = -1e30f;
                    if (cc + 1 > r0g + 8) s[j][3] = -1e30f;
                }
            }

            float mt0 = -1e30f, mt1 = -1e30f;
#pragma unroll
            for (int j = 0; j < 8; j++) {
                mt0 = fmaxf(mt0, fmaxf(s[j][0], s[j][1]));
                mt1 = fmaxf(mt1, fmaxf(s[j][2], s[j][3]));
            }
            mt0 = fmaxf(mt0, __shfl_xor_sync(0xffffffffu, mt0, 1));
            mt0 = fmaxf(mt0, __shfl_xor_sync(0xffffffffu, mt0, 2));
            mt1 = fmaxf(mt1, __shfl_xor_sync(0xffffffffu, mt1, 1));
            mt1 = fmaxf(mt1, __shfl_xor_sync(0xffffffffu, mt1, 2));
            const float mn0 = fmaxf(m0, mt0), mn1 = fmaxf(m1, mt1);
            const float corr0 = __expf(m0 - mn0), corr1 = __expf(m1 - mn1);
            m0 = mn0; m1 = mn1;
            float rs0 = 0.0f, rs1 = 0.0f;
#pragma unroll
            for (int j = 0; j < 8; j++) {
                s[j][0] = __expf(s[j][0] - mn0);
                s[j][1] = __expf(s[j][1] - mn0);
                s[j][2] = __expf(s[j][2] - mn1);
                s[j][3] = __expf(s[j][3] - mn1);
                rs0 += s[j][0] + s[j][1];
                rs1 += s[j][2] + s[j][3];
            }
            rs0 += __shfl_xor_sync(0xffffffffu, rs0, 1);
            rs0 += __shfl_xor_sync(0xffffffffu, rs0, 2);
            rs1 += __shfl_xor_sync(0xffffffffu, rs1, 1);
            rs1 += __shfl_xor_sync(0xffffffffu, rs1, 2);
            l0 = l0 * corr0 + rs0;
            l1 = l1 * corr1 + rs1;
#pragma unroll
            for (int n = 0; n < 16; n++) {
                O[n][0] *= corr0;  O[n][1] *= corr0;
                O[n][2] *= corr1;  O[n][3] *= corr1;
            }

            // ---- O += (P_hi + P_lo) . V ----
#pragma unroll
            for (int kt = 0; kt < 4; kt++) {
                uint32_t ph[4], pl[4];
                ph[0] = packh2(s[2 * kt][0], s[2 * kt][1]);
                pl[0] = packh2(s[2 * kt][0] - h2_low(ph[0]), s[2 * kt][1] - h2_high(ph[0]));
                ph[1] = packh2(s[2 * kt][2], s[2 * kt][3]);
                pl[1] = packh2(s[2 * kt][2] - h2_low(ph[1]), s[2 * kt][3] - h2_high(ph[1]));
                ph[2] = packh2(s[2 * kt + 1][0], s[2 * kt + 1][1]);
                pl[2] = packh2(s[2 * kt + 1][0] - h2_low(ph[2]), s[2 * kt + 1][1] - h2_high(ph[2]));
                ph[3] = packh2(s[2 * kt + 1][2], s[2 * kt + 1][3]);
                pl[3] = packh2(s[2 * kt + 1][2] - h2_low(ph[3]), s[2 * kt + 1][3] - h2_high(ph[3]));
#pragma unroll
                for (int g = 0; g < 8; g++) {
                    uint32_t vb[4];
                    ldm_x4_t(vb, Vb + ((kt * 16 + vrow_off) * KVS + g * 16 + vcol8) * 2);
                    mma16816h(O[2 * g],     ph, vb[0], vb[1]);
                    mma16816h(O[2 * g + 1], ph, vb[2], vb[3]);
                    mma16816h(O[2 * g],     pl, vb[0], vb[1]);
                    mma16816h(O[2 * g + 1], pl, vb[2], vb[3]);
                }
            }
        }
        __syncthreads();
    }

    // ---- normalize + split-store to g_asplit [hi|lo] fp16 ----
    const float inv0 = 1.0f / l0, inv1 = 1.0f / l1;
    const int sr0 = wrow + (lane >> 2), sr1 = sr0 + 8;
#pragma unroll
    for (int n = 0; n < 16; n++) {
        const int d = n * 8 + ((lane & 3) << 1);
        {
            float v0 = O[n][0] * inv0, v1 = O[n][1] * inv0;
            uint32_t hi = packh2(v0, v1);
            uint32_t lo = packh2(v0 - h2_low(hi), v1 - h2_high(hi));
            __half* p = g_asplit + (size_t)sr0 * GK + h * 128 + d;
            *reinterpret_cast<uint32_t*>(p)       = hi;
            *reinterpret_cast<uint32_t*>(p + DIM) = lo;
        }
        {
            float v2 = O[n][2] * inv1, v3 = O[n][3] * inv1;
            uint32_t hi = packh2(v2, v3);
            uint32_t lo = packh2(v2 - h2_low(hi), v3 - h2_high(hi));
            __half* p = g_asplit + (size_t)sr1 * GK + h * 128 + d;
            *reinterpret_cast<uint32_t*>(p)       = hi;
            *reinterpret_cast<uint32_t*>(p + DIM) = lo;
        }
    }
}

// ---------------- launch -----------------------------------------------------
// inputs: 0:x 1:start_pos 2:freqs 3:mask 4:wq 5:wk 6:wv 7:wo  (mask analytic)
extern "C" void kernel_launch(void* const* d_in, const int* in_sizes, int n_in,
                              void* d_out, int out_size)
{
    const float* x     = (const float*)d_in[0];
    const float* freqs = (const float*)d_in[2];
    const float* wq    = (const float*)d_in[4];
    const float* wk    = (const float*)d_in[5];
    const float* wv    = (const float*)d_in[6];
    const float* wo    = (const float*)d_in[7];
    float* out = (float*)d_out;

    cudaFuncSetAttribute(attn_kernel,     cudaFuncAttributeMaxDynamicSharedMemorySize, ATTN_SMEM);
    cudaFuncSetAttribute(qkv_gemm_kernel, cudaFuncAttributeMaxDynamicSharedMemorySize, GEMM_SMEM);
    cudaFuncSetAttribute(out_gemm_kernel, cudaFuncAttributeMaxDynamicSharedMemorySize, GEMM_SMEM);

    convert_w_kernel<<<dim3(DIM * DIM / 4 / 256, 1, 4), 256>>>(wq, wk, wv, wo);
    convert_x_kernel<<<SEQ * DIM / 4 / 256, 256>>>(x);
    qkv_gemm_kernel<<<dim3(SEQ / 128, DIM / 128, 3), 128, GEMM_SMEM>>>(freqs);
    attn_kernel<<<dim3(SEQ / 128, NH), 256, ATTN_SMEM>>>();
    out_gemm_kernel<<<dim3(SEQ / 128, DIM / 128, 1), 128, GEMM_SMEM>>>(out);
}

// round 12
// speedup vs baseline: 1.5676x; 1.2756x over previous
#include <cuda_runtime.h>
#include <cuda_fp16.h>
#include <math.h>
#include <stdint.h>

#define SEQ 2048
#define DIM 4096
#define NH  32
#define HD  128
#define GK  8192    // A-side 2-segment fp16 K-concat: A=[hi|lo]; B = W_hi read twice

// ---------------- scratch (__device__ globals; no cudaMalloc allowed) -------
__device__ __half g_wh[4ull * DIM * DIM];                // weights hi, single copy
__device__ __half g_xsplit[(size_t)SEQ * GK];            // x        [hi|lo]
__device__ __half g_asplit[(size_t)SEQ * GK];            // attn out [hi|(unused)]
__device__ __half g_qs[(size_t)SEQ * NH * 256];          // q per head [hi128|lo128]
__device__ __half g_ks[(size_t)SEQ * NH * 128];          // k per head, plain fp16
__device__ __half g_vs[(size_t)SEQ * NH * 128];          // v per head, plain fp16

// ---------------- PTX helpers ----------------------------------------------
__device__ __forceinline__ uint32_t smem_u32(const void* p) {
    uint32_t a;
    asm("{ .reg .u64 t; cvta.to.shared.u64 t, %1; cvt.u32.u64 %0, t; }" : "=r"(a) : "l"(p));
    return a;
}
__device__ __forceinline__ void cp_async16(uint32_t dst, const void* src) {
    asm volatile("cp.async.cg.shared.global [%0], [%1], 16;" :: "r"(dst), "l"(src));
}
#define CP_COMMIT()  asm volatile("cp.async.commit_group;" ::: "memory")
#define CP_WAIT(n)   asm volatile("cp.async.wait_group %0;" :: "n"(n) : "memory")

__device__ __forceinline__ void ldm_x4(uint32_t* r, uint32_t addr) {
    asm volatile("ldmatrix.sync.aligned.m8n8.x4.shared.b16 {%0,%1,%2,%3}, [%4];"
        : "=r"(r[0]), "=r"(r[1]), "=r"(r[2]), "=r"(r[3]) : "r"(addr));
}
__device__ __forceinline__ void ldm_x4_t(uint32_t* r, uint32_t addr) {
    asm volatile("ldmatrix.sync.aligned.m8n8.x4.trans.shared.b16 {%0,%1,%2,%3}, [%4];"
        : "=r"(r[0]), "=r"(r[1]), "=r"(r[2]), "=r"(r[3]) : "r"(addr));
}
// fp16 mma, fp32 accum
__device__ __forceinline__ void mma16816h(float* c, const uint32_t* a, uint32_t b0, uint32_t b1) {
    asm volatile(
        "mma.sync.aligned.m16n8k16.row.col.f32.f16.f16.f32 "
        "{%0,%1,%2,%3}, {%4,%5,%6,%7}, {%8,%9}, {%0,%1,%2,%3};"
        : "+f"(c[0]), "+f"(c[1]), "+f"(c[2]), "+f"(c[3])
        : "r"(a[0]), "r"(a[1]), "r"(a[2]), "r"(a[3]), "r"(b0), "r"(b1));
}
__device__ __forceinline__ uint32_t packh2(float lo, float hi) {
    __half2 h = __floats2half2_rn(lo, hi);
    return *reinterpret_cast<uint32_t*>(&h);
}
__device__ __forceinline__ float h2_low(uint32_t r)  { return __low2float(*reinterpret_cast<__half2*>(&r)); }
__device__ __forceinline__ float h2_high(uint32_t r) { return __high2float(*reinterpret_cast<__half2*>(&r)); }

// ---------------- fp32 -> fp16 hi/lo split converters -----------------------
__device__ __forceinline__ void split4h(const float4 v, __half* hi, __half* lo) {
    float f[4] = {v.x, v.y, v.z, v.w};
#pragma unroll
    for (int i = 0; i < 4; i++) {
        hi[i] = __float2half_rn(f[i]);
        lo[i] = __float2half_rn(f[i] - __half2float(hi[i]));
    }
}

// Weights: single hi copy [DIM x DIM]
__global__ __launch_bounds__(256) void convert_w_kernel(
    const float* __restrict__ w0, const float* __restrict__ w1,
    const float* __restrict__ w2, const float* __restrict__ w3)
{
    const float* w = (blockIdx.z == 0) ? w0 : (blockIdx.z == 1) ? w1 :
                     (blockIdx.z == 2) ? w2 : w3;
    __half* dst = g_wh + (size_t)blockIdx.z * DIM * DIM;
    int idx = blockIdx.x * 256 + threadIdx.x;
    float4 v = reinterpret_cast<const float4*>(w)[idx];
    __half hi[4];
    hi[0] = __float2half_rn(v.x); hi[1] = __float2half_rn(v.y);
    hi[2] = __float2half_rn(v.z); hi[3] = __float2half_rn(v.w);
    *reinterpret_cast<uint2*>(dst + (size_t)idx * 4) = *reinterpret_cast<uint2*>(hi);
}

// x: [hi | lo]
__global__ __launch_bounds__(256) void convert_x_kernel(const float* __restrict__ x)
{
    int idx = blockIdx.x * 256 + threadIdx.x;
    int row = idx >> 10;
    int c4  = (idx & 1023) << 2;
    __half hi[4], lo[4];
    split4h(reinterpret_cast<const float4*>(x)[idx], hi, lo);
    size_t base = (size_t)row * GK + c4;
    *reinterpret_cast<uint2*>(g_xsplit + base)       = *reinterpret_cast<uint2*>(hi);
    *reinterpret_cast<uint2*>(g_xsplit + base + DIM) = *reinterpret_cast<uint2*>(lo);
}

// ---------------- HMMA fp16 GEMM: 4 warps, warp tile 64x64 ------------------
// C[128x128] = A'[M,nk*BK-slice] . W_hi^T.  k<128 covers A-hi; k>=128 A-lo.
// 128 threads, 4 warps (2m x 2n), warp tile 64x64, BK=32, 3-stage cp.async.
#define BK 32
#define NKSTEP (GK / BK)     // 256 (full compensation)
#define HALFK (NKSTEP / 2)   // 128 (hi only — compensation dropped)
#define ASTR 40
#define GSTAGES 3
#define GEMM_SMEM (GSTAGES * 2 * 128 * ASTR * (int)sizeof(__half))  // 61440

__device__ __forceinline__ void hgemm_body(
    const __half* __restrict__ A,
    const __half* __restrict__ B,          // [4096 x 4096] hi
    float* __restrict__ C,                 // omode 0
    __half* __restrict__ hdst,             // omode 1 (q split) / 2 (plain kv)
    int omode, int nk,
    const float* __restrict__ freqs, int rope, float qsc,
    int m0, int n0)
{
    extern __shared__ __half gsm[];
    __half* sA = gsm;                          // GSTAGES x 128 x ASTR
    __half* sB = gsm + GSTAGES * 128 * ASTR;   // GSTAGES x 128 x ASTR

    const int tid  = threadIdx.x;
    const int wid  = tid >> 5;
    const int lane = tid & 31;
    const int wm   = wid >> 1;   // 0..1 -> rows wm*64
    const int wn   = wid & 1;    // 0..1 -> cols wn*64

    float acc[4][8][4];
#pragma unroll
    for (int mi = 0; mi < 4; mi++)
#pragma unroll
        for (int ni = 0; ni < 8; ni++)
#pragma unroll
            for (int j = 0; j < 4; j++) acc[mi][ni][j] = 0.0f;

    const __half* agp = A + (size_t)m0 * GK;
    const __half* bgp = B + (size_t)n0 * DIM;

    auto load_tile = [&](int kstep, int s) {
        const size_t ka = (size_t)kstep * BK;
        const size_t kb = ka & (DIM - 1);
#pragma unroll
        for (int l = 0; l < 4; l++) {
            int i = tid + l * 128;
            int r = i >> 2, seg = i & 3;
            cp_async16(smem_u32(sA + (s * 128 + r) * ASTR + seg * 8), agp + (size_t)r * GK  + ka + seg * 8);
            cp_async16(smem_u32(sB + (s * 128 + r) * ASTR + seg * 8), bgp + (size_t)r * DIM + kb + seg * 8);
        }
        CP_COMMIT();
    };

    load_tile(0, 0);
    load_tile(1, 1);

    for (int k = 0; k < nk; k++) {
        if (k + 1 < nk) { CP_WAIT(1); } else { CP_WAIT(0); }
        __syncthreads();
        if (k + 2 < nk) load_tile(k + 2, (k + 2) % GSTAGES);

        const int s = k % GSTAGES;
#pragma unroll
        for (int kk = 0; kk < 2; kk++) {
            const int k0 = kk * 16;
            uint32_t af[4][4], bf[8][2];
#pragma unroll
            for (int mi = 0; mi < 4; mi++) {
                int row = wm * 64 + mi * 16 + (lane & 15);
                ldm_x4(af[mi], smem_u32(sA + (s * 128 + row) * ASTR + k0 + ((lane >> 4) << 3)));
            }
#pragma unroll
            for (int np = 0; np < 4; np++) {
                int rown = wn * 64 + np * 16 + ((lane >> 4) << 3) + (lane & 7);
                uint32_t b[4];
                ldm_x4(b, smem_u32(sB + (s * 128 + rown) * ASTR + k0 + (((lane >> 3) & 1) << 3)));
                bf[2 * np][0] = b[0];  bf[2 * np][1] = b[1];
                bf[2 * np + 1][0] = b[2];  bf[2 * np + 1][1] = b[3];
            }
#pragma unroll
            for (int mi = 0; mi < 4; mi++)
#pragma unroll
                for (int ni = 0; ni < 8; ni++)
                    mma16816h(acc[mi][ni], af[mi], bf[ni][0], bf[ni][1]);
        }
    }

#pragma unroll
    for (int mi = 0; mi < 4; mi++) {
        const int ra = m0 + wm * 64 + mi * 16 + (lane >> 2);
        const int rb = ra + 8;
#pragma unroll
        for (int ni = 0; ni < 8; ni++) {
            const int col = n0 + wn * 64 + ni * 8 + ((lane & 3) << 1);
            float d0 = acc[mi][ni][0], d1 = acc[mi][ni][1];
            float d2 = acc[mi][ni][2], d3 = acc[mi][ni][3];
            if (rope) {
                const int hd = col & (HD - 1);          // even
                float ca = freqs[ra * HD + hd], sa = freqs[ra * HD + hd + 1];
                float cb = freqs[rb * HD + hd], sb = freqs[rb * HD + hd + 1];
                d0 *= (ca - sa) * qsc;  d1 *= (ca + sa) * qsc;
                d2 *= (cb - sb) * qsc;  d3 *= (cb + sb) * qsc;
            }
            if (omode == 1) {                       // q: split [hi|lo]
                const int head = col >> 7, d = col & 127;
                __half* pa = hdst + ((size_t)ra * NH + head) * 256 + d;
                uint32_t hi = packh2(d0, d1);
                uint32_t lo = packh2(d0 - h2_low(hi), d1 - h2_high(hi));
                *reinterpret_cast<uint32_t*>(pa)       = hi;
                *reinterpret_cast<uint32_t*>(pa + 128) = lo;
                __half* pb = hdst + ((size_t)rb * NH + head) * 256 + d;
                hi = packh2(d2, d3);
                lo = packh2(d2 - h2_low(hi), d3 - h2_high(hi));
                *reinterpret_cast<uint32_t*>(pb)       = hi;
                *reinterpret_cast<uint32_t*>(pb + 128) = lo;
            } else if (omode == 2) {                // k/v: plain fp16
                const int head = col >> 7, d = col & 127;
                *reinterpret_cast<uint32_t*>(hdst + ((size_t)ra * NH + head) * 128 + d) = packh2(d0, d1);
                *reinterpret_cast<uint32_t*>(hdst + ((size_t)rb * NH + head) * 128 + d) = packh2(d2, d3);
            } else {
                *reinterpret_cast<float2*>(&C[(size_t)ra * DIM + col]) = make_float2(d0, d1);
                *reinterpret_cast<float2*>(&C[(size_t)rb * DIM + col]) = make_float2(d2, d3);
            }
        }
    }
}

__global__ __launch_bounds__(128, 2) void qkv_gemm_kernel(const float* __restrict__ freqs)
{
    const int z = blockIdx.z;
    const __half* B = g_wh + (size_t)z * DIM * DIM;
    __half* dst = (z == 0) ? g_qs : (z == 1) ? g_ks : g_vs;
    const float qsc = (z == 0) ? 0.08838834764831845f : 1.0f;
    // V projection: drop x_lo compensation (nk=HALFK) — error ~2.4e-4, linear path
    const int nk = (z == 2) ? HALFK : NKSTEP;
    hgemm_body(g_xsplit, B, nullptr, dst, (z == 0) ? 1 : 2, nk, freqs, (z < 2) ? 1 : 0, qsc,
               blockIdx.x * 128, blockIdx.y * 128);
}

__global__ __launch_bounds__(128, 2) void out_gemm_kernel(float* __restrict__ out)
{
    // out-proj: drop a_lo compensation (nk=HALFK)
    hgemm_body(g_asplit, g_wh + 3ull * DIM * DIM, out, nullptr, 0, HALFK, nullptr, 0, 1.0f,
               blockIdx.x * 128, blockIdx.y * 128);
}

// ---------------- fp16 flash attention (R11, heavy-tiles-first) -------------
// CTA: 128 q x 64 kv, 8 warps. q split [hi|lo]; K,V plain fp16.
// S = q_hi.K + q_lo.K ; O += P_hi.V + P_lo.V
#define AQS 264                       // q smem row stride (256 + 8)
#define KVS 136                       // k/v smem row stride (128 + 8)
#define ATTN_SMEM ((128 * AQS + 4 * 64 * KVS) * (int)sizeof(__half))

__global__ __launch_bounds__(256, 1) void attn_kernel()
{
    extern __shared__ __half sm_attn[];
    __half* sQ = sm_attn;                  // 128 x AQS
    __half* sK = sQ + 128 * AQS;           // 2 x 64 x KVS
    __half* sV = sK + 2 * 64 * KVS;        // 2 x 64 x KVS

    const int h   = blockIdx.y;
    const int q0  = (gridDim.x - 1 - blockIdx.x) * 128;   // heavy tiles first
    const int tid = threadIdx.x;
    const int wid = tid >> 5, lane = tid & 31;

    for (int i = tid; i < 128 * 32; i += 256) {
        int r = i >> 5, c = i & 31;
        cp_async16(smem_u32(sQ + r * AQS) + c * 16,
                   g_qs + ((size_t)(q0 + r) * NH + h) * 256 + c * 8);
    }
    CP_COMMIT();

    const int nt = q0 / 64 + 2;

    auto load_kv = [&](int t, int s) {
        for (int i = tid; i < 64 * 16 * 2; i += 256) {
            int half_sel = i >= 64 * 16;
            int j = i & (64 * 16 - 1);
            int r = j >> 4, c = j & 15;
            size_t src = ((size_t)(t * 64 + r) * NH + h) * 128 + c * 8;
            __half* dst = (half_sel ? sV : sK) + (s * 64 + r) * KVS + c * 8;
            cp_async16(smem_u32(dst), (half_sel ? g_vs : g_ks) + src);
        }
        CP_COMMIT();
    };
    load_kv(0, 0);

    float m0 = -1e30f, m1 = -1e30f, l0 = 0.0f, l1 = 0.0f;
    float O[16][4];
#pragma unroll
    for (int n = 0; n < 16; n++)
#pragma unroll
        for (int j = 0; j < 4; j++) O[n][j] = 0.0f;

    const int wrow = q0 + wid * 16;
    const int r0g  = wrow + (lane >> 2);
    const uint32_t Qb = smem_u32(sQ);
    const uint32_t qrow_off = (uint32_t)((wid * 16 + (lane & 15)) * AQS + ((lane >> 4) << 3));
    const uint32_t krow = (uint32_t)(((lane >> 4) << 3) + (lane & 7));
    const uint32_t kcol = (uint32_t)(((lane >> 3) & 1) << 3);
    const uint32_t vrow_off = (uint32_t)(lane & 15);
    const uint32_t vcol8 = (uint32_t)((lane >> 4) << 3);

    for (int t = 0; t < nt; t++) {
        if (t + 1 < nt) { load_kv(t + 1, (t + 1) & 1); CP_WAIT(1); }
        else           { CP_WAIT(0); }
        __syncthreads();
        const int k0 = t * 64;

        if (k0 <= wrow + 15) {
            const uint32_t Kb = smem_u32(sK + (t & 1) * 64 * KVS);
            const uint32_t Vb = smem_u32(sV + (t & 1) * 64 * KVS);

            float s[8][4];
#pragma unroll
            for (int j = 0; j < 8; j++)
#pragma unroll
                for (int i = 0; i < 4; i++) s[j][i] = 0.0f;

            // ---- S = (q_hi + q_lo) . K ----
#pragma unroll
            for (int kk = 0; kk < 8; kk++) {
                uint32_t qh[4], ql[4];
                ldm_x4(qh, Qb + (qrow_off + kk * 16) * 2);
                ldm_x4(ql, Qb + (qrow_off + 128 + kk * 16) * 2);
#pragma unroll
                for (int g = 0; g < 4; g++) {
                    uint32_t kb[4];
                    ldm_x4(kb, Kb + ((g * 16 + krow) * KVS + kcol + kk * 16) * 2);
                    mma16816h(s[2 * g],     qh, kb[0], kb[1]);
                    mma16816h(s[2 * g + 1], qh, kb[2], kb[3]);
                    mma16816h(s[2 * g],     ql, kb[0], kb[1]);
                    mma16816h(s[2 * g + 1], ql, kb[2], kb[3]);
                }
            }

            if (k0 + 63 > wrow) {
                const int c0 = k0 + ((lane & 3) << 1);
#pragma unroll
                for (int j = 0; j < 8; j++) {
                    int cc = c0 + j * 8;
                    if (cc     > r0g)     s[j][0] = -1e30f;
                    if (cc + 1 > r0g)     s[j][1] = -1e30f;
                    if (cc     > r0g + 8) s[j][2] = -1e30f;
                    if (cc + 1 > r0g + 8) s[j][3] = -1e30f;
                }
            }

            float mt0 = -1e30f, mt1 = -1e30f;
#pragma unroll
            for (int j = 0; j < 8; j++) {
                mt0 = fmaxf(mt0, fmaxf(s[j][0], s[j][1]));
                mt1 = fmaxf(mt1, fmaxf(s[j][2], s[j][3]));
            }
            mt0 = fmaxf(mt0, __shfl_xor_sync(0xffffffffu, mt0, 1));
            mt0 = fmaxf(mt0, __shfl_xor_sync(0xffffffffu, mt0, 2));
            mt1 = fmaxf(mt1, __shfl_xor_sync(0xffffffffu, mt1, 1));
            mt1 = fmaxf(mt1, __shfl_xor_sync(0xffffffffu, mt1, 2));
            const float mn0 = fmaxf(m0, mt0), mn1 = fmaxf(m1, mt1);
            const float corr0 = __expf(m0 - mn0), corr1 = __expf(m1 - mn1);
            m0 = mn0; m1 = mn1;
            float rs0 = 0.0f, rs1 = 0.0f;
#pragma unroll
            for (int j = 0; j < 8; j++) {
                s[j][0] = __expf(s[j][0] - mn0);
                s[j][1] = __expf(s[j][1] - mn0);
                s[j][2] = __expf(s[j][2] - mn1);
                s[j][3] = __expf(s[j][3] - mn1);
                rs0 += s[j][0] + s[j][1];
                rs1 += s[j][2] + s[j][3];
            }
            rs0 += __shfl_xor_sync(0xffffffffu, rs0, 1);
            rs0 += __shfl_xor_sync(0xffffffffu, rs0, 2);
            rs1 += __shfl_xor_sync(0xffffffffu, rs1, 1);
            rs1 += __shfl_xor_sync(0xffffffffu, rs1, 2);
            l0 = l0 * corr0 + rs0;
            l1 = l1 * corr1 + rs1;
#pragma unroll
            for (int n = 0; n < 16; n++) {
                O[n][0] *= corr0;  O[n][1] *= corr0;
                O[n][2] *= corr1;  O[n][3] *= corr1;
            }

            // ---- O += (P_hi + P_lo) . V ----
#pragma unroll
            for (int kt = 0; kt < 4; kt++) {
                uint32_t ph[4], pl[4];
                ph[0] = packh2(s[2 * kt][0], s[2 * kt][1]);
                pl[0] = packh2(s[2 * kt][0] - h2_low(ph[0]), s[2 * kt][1] - h2_high(ph[0]));
                ph[1] = packh2(s[2 * kt][2], s[2 * kt][3]);
                pl[1] = packh2(s[2 * kt][2] - h2_low(ph[1]), s[2 * kt][3] - h2_high(ph[1]));
                ph[2] = packh2(s[2 * kt + 1][0], s[2 * kt + 1][1]);
                pl[2] = packh2(s[2 * kt + 1][0] - h2_low(ph[2]), s[2 * kt + 1][1] - h2_high(ph[2]));
                ph[3] = packh2(s[2 * kt + 1][2], s[2 * kt + 1][3]);
                pl[3] = packh2(s[2 * kt + 1][2] - h2_low(ph[3]), s[2 * kt + 1][3] - h2_high(ph[3]));
#pragma unroll
                for (int g = 0; g < 8; g++) {
                    uint32_t vb[4];
                    ldm_x4_t(vb, Vb + ((kt * 16 + vrow_off) * KVS + g * 16 + vcol8) * 2);
                    mma16816h(O[2 * g],     ph, vb[0], vb[1]);
                    mma16816h(O[2 * g + 1], ph, vb[2], vb[3]);
                    mma16816h(O[2 * g],     pl, vb[0], vb[1]);
                    mma16816h(O[2 * g + 1], pl, vb[2], vb[3]);
                }
            }
        }
        __syncthreads();
    }

    // ---- normalize + store hi to g_asplit (out-proj reads hi only) ----
    const float inv0 = 1.0f / l0, inv1 = 1.0f / l1;
    const int sr0 = wrow + (lane >> 2), sr1 = sr0 + 8;
#pragma unroll
    for (int n = 0; n < 16; n++) {
        const int d = n * 8 + ((lane & 3) << 1);
        {
            float v0 = O[n][0] * inv0, v1 = O[n][1] * inv0;
            __half* p = g_asplit + (size_t)sr0 * GK + h * 128 + d;
            *reinterpret_cast<uint32_t*>(p) = packh2(v0, v1);
        }
        {
            float v2 = O[n][2] * inv1, v3 = O[n][3] * inv1;
            __half* p = g_asplit + (size_t)sr1 * GK + h * 128 + d;
            *reinterpret_cast<uint32_t*>(p) = packh2(v2, v3);
        }
    }
}

// ---------------- launch -----------------------------------------------------
// inputs: 0:x 1:start_pos 2:freqs 3:mask 4:wq 5:wk 6:wv 7:wo  (mask analytic)
extern "C" void kernel_launch(void* const* d_in, const int* in_sizes, int n_in,
                              void* d_out, int out_size)
{
    const float* x     = (const float*)d_in[0];
    const float* freqs = (const float*)d_in[2];
    const float* wq    = (const float*)d_in[4];
    const float* wk    = (const float*)d_in[5];
    const float* wv    = (const float*)d_in[6];
    const float* wo    = (const float*)d_in[7];
    float* out = (float*)d_out;

    cudaFuncSetAttribute(attn_kernel,     cudaFuncAttributeMaxDynamicSharedMemorySize, ATTN_SMEM);
    cudaFuncSetAttribute(qkv_gemm_kernel, cudaFuncAttributeMaxDynamicSharedMemorySize, GEMM_SMEM);
    cudaFuncSetAttribute(out_gemm_kernel, cudaFuncAttributeMaxDynamicSharedMemorySize, GEMM_SMEM);

    convert_w_kernel<<<dim3(DIM * DIM / 4 / 256, 1, 4), 256>>>(wq, wk, wv, wo);
    convert_x_kernel<<<SEQ * DIM / 4 / 256, 256>>>(x);
    qkv_gemm_kernel<<<dim3(SEQ / 128, DIM / 128, 3), 128, GEMM_SMEM>>>(freqs);
    attn_kernel<<<dim3(SEQ / 128, NH), 256, ATTN_SMEM>>>();
    out_gemm_kernel<<<dim3(SEQ / 128, DIM / 128, 1), 128, GEMM_SMEM>>>(out);
}

// round 13
// speedup vs baseline: 2.0375x; 1.2997x over previous
#include <cuda_runtime.h>
#include <cuda_fp16.h>
#include <math.h>
#include <stdint.h>

#define SEQ 2048
#define DIM 4096
#define NH  32
#define HD  128

// ---------------- scratch (__device__ globals; no cudaMalloc allowed) -------
__device__ __half g_wh[4ull * DIM * DIM];                // weights hi, single copy
__device__ __half g_x [(size_t)SEQ * DIM];               // x  (fp16 hi)
__device__ __half g_a [(size_t)SEQ * DIM];               // attn out (fp16 hi)
__device__ __half g_qs[(size_t)SEQ * NH * 256];          // q per head [hi128|lo128]
__device__ __half g_ks[(size_t)SEQ * NH * 128];          // k per head, plain fp16
__device__ __half g_vs[(size_t)SEQ * NH * 128];          // v per head, plain fp16

// ---------------- PTX helpers ----------------------------------------------
__device__ __forceinline__ uint32_t smem_u32(const void* p) {
    uint32_t a;
    asm("{ .reg .u64 t; cvta.to.shared.u64 t, %1; cvt.u32.u64 %0, t; }" : "=r"(a) : "l"(p));
    return a;
}
__device__ __forceinline__ void cp_async16(uint32_t dst, const void* src) {
    asm volatile("cp.async.cg.shared.global [%0], [%1], 16;" :: "r"(dst), "l"(src));
}
#define CP_COMMIT()  asm volatile("cp.async.commit_group;" ::: "memory")
#define CP_WAIT(n)   asm volatile("cp.async.wait_group %0;" :: "n"(n) : "memory")

__device__ __forceinline__ void ldm_x4(uint32_t* r, uint32_t addr) {
    asm volatile("ldmatrix.sync.aligned.m8n8.x4.shared.b16 {%0,%1,%2,%3}, [%4];"
        : "=r"(r[0]), "=r"(r[1]), "=r"(r[2]), "=r"(r[3]) : "r"(addr));
}
__device__ __forceinline__ void ldm_x4_t(uint32_t* r, uint32_t addr) {
    asm volatile("ldmatrix.sync.aligned.m8n8.x4.trans.shared.b16 {%0,%1,%2,%3}, [%4];"
        : "=r"(r[0]), "=r"(r[1]), "=r"(r[2]), "=r"(r[3]) : "r"(addr));
}
// fp16 mma, fp32 accum
__device__ __forceinline__ void mma16816h(float* c, const uint32_t* a, uint32_t b0, uint32_t b1) {
    asm volatile(
        "mma.sync.aligned.m16n8k16.row.col.f32.f16.f16.f32 "
        "{%0,%1,%2,%3}, {%4,%5,%6,%7}, {%8,%9}, {%0,%1,%2,%3};"
        : "+f"(c[0]), "+f"(c[1]), "+f"(c[2]), "+f"(c[3])
        : "r"(a[0]), "r"(a[1]), "r"(a[2]), "r"(a[3]), "r"(b0), "r"(b1));
}
__device__ __forceinline__ uint32_t packh2(float lo, float hi) {
    __half2 h = __floats2half2_rn(lo, hi);
    return *reinterpret_cast<uint32_t*>(&h);
}
__device__ __forceinline__ float h2_low(uint32_t r)  { return __low2float(*reinterpret_cast<__half2*>(&r)); }
__device__ __forceinline__ float h2_high(uint32_t r) { return __high2float(*reinterpret_cast<__half2*>(&r)); }

// ---------------- converters -------------------------------------------------
// Weights: single hi copy [DIM x DIM]
__global__ __launch_bounds__(256) void convert_w_kernel(
    const float* __restrict__ w0, const float* __restrict__ w1,
    const float* __restrict__ w2, const float* __restrict__ w3)
{
    const float* w = (blockIdx.z == 0) ? w0 : (blockIdx.z == 1) ? w1 :
                     (blockIdx.z == 2) ? w2 : w3;
    __half* dst = g_wh + (size_t)blockIdx.z * DIM * DIM;
    int idx = blockIdx.x * 256 + threadIdx.x;
    float4 v = reinterpret_cast<const float4*>(w)[idx];
    __half hi[4];
    hi[0] = __float2half_rn(v.x); hi[1] = __float2half_rn(v.y);
    hi[2] = __float2half_rn(v.z); hi[3] = __float2half_rn(v.w);
    *reinterpret_cast<uint2*>(dst + (size_t)idx * 4) = *reinterpret_cast<uint2*>(hi);
}

// x: fp16 hi only
__global__ __launch_bounds__(256) void convert_x_kernel(const float* __restrict__ x)
{
    int idx = blockIdx.x * 256 + threadIdx.x;
    float4 v = reinterpret_cast<const float4*>(x)[idx];
    __half hi[4];
    hi[0] = __float2half_rn(v.x); hi[1] = __float2half_rn(v.y);
    hi[2] = __float2half_rn(v.z); hi[3] = __float2half_rn(v.w);
    *reinterpret_cast<uint2*>(g_x + (size_t)idx * 4) = *reinterpret_cast<uint2*>(hi);
}

// ---------------- HMMA fp16 GEMM: 4 warps, warp tile 64x64 ------------------
// C[128x128] = A[M,DIM] . B[N,DIM]^T, plain fp16, f32 accum.
// 128 threads, 4 warps (2m x 2n), BK=32, 3-stage cp.async.
#define BK 32
#define NKSTEP (DIM / BK)    // 128
#define ASTR 40
#define GSTAGES 3
#define GEMM_SMEM (GSTAGES * 2 * 128 * ASTR * (int)sizeof(__half))  // 61440

__device__ __forceinline__ void hgemm_body(
    const __half* __restrict__ A,          // [M x DIM]
    const __half* __restrict__ B,          // [4096 x 4096]
    float* __restrict__ C,                 // omode 0
    __half* __restrict__ hdst,             // omode 1 (q split) / 2 (plain kv)
    int omode,
    const float* __restrict__ freqs, int rope, float qsc,
    int m0, int n0)
{
    extern __shared__ __half gsm[];
    __half* sA = gsm;                          // GSTAGES x 128 x ASTR
    __half* sB = gsm + GSTAGES * 128 * ASTR;   // GSTAGES x 128 x ASTR

    const int tid  = threadIdx.x;
    const int wid  = tid >> 5;
    const int lane = tid & 31;
    const int wm   = wid >> 1;   // 0..1 -> rows wm*64
    const int wn   = wid & 1;    // 0..1 -> cols wn*64

    float acc[4][8][4];
#pragma unroll
    for (int mi = 0; mi < 4; mi++)
#pragma unroll
        for (int ni = 0; ni < 8; ni++)
#pragma unroll
            for (int j = 0; j < 4; j++) acc[mi][ni][j] = 0.0f;

    const __half* agp = A + (size_t)m0 * DIM;
    const __half* bgp = B + (size_t)n0 * DIM;

    auto load_tile = [&](int kstep, int s) {
        const size_t ka = (size_t)kstep * BK;
#pragma unroll
        for (int l = 0; l < 4; l++) {
            int i = tid + l * 128;
            int r = i >> 2, seg = i & 3;
            cp_async16(smem_u32(sA + (s * 128 + r) * ASTR + seg * 8), agp + (size_t)r * DIM + ka + seg * 8);
            cp_async16(smem_u32(sB + (s * 128 + r) * ASTR + seg * 8), bgp + (size_t)r * DIM + ka + seg * 8);
        }
        CP_COMMIT();
    };

    load_tile(0, 0);
    load_tile(1, 1);

    for (int k = 0; k < NKSTEP; k++) {
        if (k + 1 < NKSTEP) { CP_WAIT(1); } else { CP_WAIT(0); }
        __syncthreads();
        if (k + 2 < NKSTEP) load_tile(k + 2, (k + 2) % GSTAGES);

        const int s = k % GSTAGES;
#pragma unroll
        for (int kk = 0; kk < 2; kk++) {
            const int k0 = kk * 16;
            uint32_t af[4][4], bf[8][2];
#pragma unroll
            for (int mi = 0; mi < 4; mi++) {
                int row = wm * 64 + mi * 16 + (lane & 15);
                ldm_x4(af[mi], smem_u32(sA + (s * 128 + row) * ASTR + k0 + ((lane >> 4) << 3)));
            }
#pragma unroll
            for (int np = 0; np < 4; np++) {
                int rown = wn * 64 + np * 16 + ((lane >> 4) << 3) + (lane & 7);
                uint32_t b[4];
                ldm_x4(b, smem_u32(sB + (s * 128 + rown) * ASTR + k0 + (((lane >> 3) & 1) << 3)));
                bf[2 * np][0] = b[0];  bf[2 * np][1] = b[1];
                bf[2 * np + 1][0] = b[2];  bf[2 * np + 1][1] = b[3];
            }
#pragma unroll
            for (int mi = 0; mi < 4; mi++)
#pragma unroll
                for (int ni = 0; ni < 8; ni++)
                    mma16816h(acc[mi][ni], af[mi], bf[ni][0], bf[ni][1]);
        }
    }

#pragma unroll
    for (int mi = 0; mi < 4; mi++) {
        const int ra = m0 + wm * 64 + mi * 16 + (lane >> 2);
        const int rb = ra + 8;
#pragma unroll
        for (int ni = 0; ni < 8; ni++) {
            const int col = n0 + wn * 64 + ni * 8 + ((lane & 3) << 1);
            float d0 = acc[mi][ni][0], d1 = acc[mi][ni][1];
            float d2 = acc[mi][ni][2], d3 = acc[mi][ni][3];
            if (rope) {
                const int hd = col & (HD - 1);          // even
                float ca = freqs[ra * HD + hd], sa = freqs[ra * HD + hd + 1];
                float cb = freqs[rb * HD + hd], sb = freqs[rb * HD + hd + 1];
                d0 *= (ca - sa) * qsc;  d1 *= (ca + sa) * qsc;
                d2 *= (cb - sb) * qsc;  d3 *= (cb + sb) * qsc;
            }
            if (omode == 1) {                       // q: split [hi|lo]
                const int head = col >> 7, d = col & 127;
                __half* pa = hdst + ((size_t)ra * NH + head) * 256 + d;
                uint32_t hi = packh2(d0, d1);
                uint32_t lo = packh2(d0 - h2_low(hi), d1 - h2_high(hi));
                *reinterpret_cast<uint32_t*>(pa)       = hi;
                *reinterpret_cast<uint32_t*>(pa + 128) = lo;
                __half* pb = hdst + ((size_t)rb * NH + head) * 256 + d;
                hi = packh2(d2, d3);
                lo = packh2(d2 - h2_low(hi), d3 - h2_high(hi));
                *reinterpret_cast<uint32_t*>(pb)       = hi;
                *reinterpret_cast<uint32_t*>(pb + 128) = lo;
            } else if (omode == 2) {                // k/v: plain fp16
                const int head = col >> 7, d = col & 127;
                *reinterpret_cast<uint32_t*>(hdst + ((size_t)ra * NH + head) * 128 + d) = packh2(d0, d1);
                *reinterpret_cast<uint32_t*>(hdst + ((size_t)rb * NH + head) * 128 + d) = packh2(d2, d3);
            } else {
                *reinterpret_cast<float2*>(&C[(size_t)ra * DIM + col]) = make_float2(d0, d1);
                *reinterpret_cast<float2*>(&C[(size_t)rb * DIM + col]) = make_float2(d2, d3);
            }
        }
    }
}

__global__ __launch_bounds__(128, 2) void qkv_gemm_kernel(const float* __restrict__ freqs)
{
    const int z = blockIdx.z;
    const __half* B = g_wh + (size_t)z * DIM * DIM;
    __half* dst = (z == 0) ? g_qs : (z == 1) ? g_ks : g_vs;
    const float qsc = (z == 0) ? 0.08838834764831845f : 1.0f;
    hgemm_body(g_x, B, nullptr, dst, (z == 0) ? 1 : 2, freqs, (z < 2) ? 1 : 0, qsc,
               blockIdx.x * 128, blockIdx.y * 128);
}

__global__ __launch_bounds__(128, 2) void out_gemm_kernel(float* __restrict__ out)
{
    hgemm_body(g_a, g_wh + 3ull * DIM * DIM, out, nullptr, 0, nullptr, 0, 1.0f,
               blockIdx.x * 128, blockIdx.y * 128);
}

// ---------------- fp16 flash attention (R12, heavy-tiles-first) -------------
// CTA: 128 q x 64 kv, 8 warps. q split [hi|lo]; K,V plain fp16.
// S = q_hi.K + q_lo.K ; O += P_hi.V + P_lo.V
#define AQS 264                       // q smem row stride (256 + 8)
#define KVS 136                       // k/v smem row stride (128 + 8)
#define ATTN_SMEM ((128 * AQS + 4 * 64 * KVS) * (int)sizeof(__half))

__global__ __launch_bounds__(256, 1) void attn_kernel()
{
    extern __shared__ __half sm_attn[];
    __half* sQ = sm_attn;                  // 128 x AQS
    __half* sK = sQ + 128 * AQS;           // 2 x 64 x KVS
    __half* sV = sK + 2 * 64 * KVS;        // 2 x 64 x KVS

    const int h   = blockIdx.y;
    const int q0  = (gridDim.x - 1 - blockIdx.x) * 128;   // heavy tiles first
    const int tid = threadIdx.x;
    const int wid = tid >> 5, lane = tid & 31;

    for (int i = tid; i < 128 * 32; i += 256) {
        int r = i >> 5, c = i & 31;
        cp_async16(smem_u32(sQ + r * AQS) + c * 16,
                   g_qs + ((size_t)(q0 + r) * NH + h) * 256 + c * 8);
    }
    CP_COMMIT();

    const int nt = q0 / 64 + 2;

    auto load_kv = [&](int t, int s) {
        for (int i = tid; i < 64 * 16 * 2; i += 256) {
            int half_sel = i >= 64 * 16;
            int j = i & (64 * 16 - 1);
            int r = j >> 4, c = j & 15;
            size_t src = ((size_t)(t * 64 + r) * NH + h) * 128 + c * 8;
            __half* dst = (half_sel ? sV : sK) + (s * 64 + r) * KVS + c * 8;
            cp_async16(smem_u32(dst), (half_sel ? g_vs : g_ks) + src);
        }
        CP_COMMIT();
    };
    load_kv(0, 0);

    float m0 = -1e30f, m1 = -1e30f, l0 = 0.0f, l1 = 0.0f;
    float O[16][4];
#pragma unroll
    for (int n = 0; n < 16; n++)
#pragma unroll
        for (int j = 0; j < 4; j++) O[n][j] = 0.0f;

    const int wrow = q0 + wid * 16;
    const int r0g  = wrow + (lane >> 2);
    const uint32_t Qb = smem_u32(sQ);
    const uint32_t qrow_off = (uint32_t)((wid * 16 + (lane & 15)) * AQS + ((lane >> 4) << 3));
    const uint32_t krow = (uint32_t)(((lane >> 4) << 3) + (lane & 7));
    const uint32_t kcol = (uint32_t)(((lane >> 3) & 1) << 3);
    const uint32_t vrow_off = (uint32_t)(lane & 15);
    const uint32_t vcol8 = (uint32_t)((lane >> 4) << 3);

    for (int t = 0; t < nt; t++) {
        if (t + 1 < nt) { load_kv(t + 1, (t + 1) & 1); CP_WAIT(1); }
        else           { CP_WAIT(0); }
        __syncthreads();
        const int k0 = t * 64;

        if (k0 <= wrow + 15) {
            const uint32_t Kb = smem_u32(sK + (t & 1) * 64 * KVS);
            const uint32_t Vb = smem_u32(sV + (t & 1) * 64 * KVS);

            float s[8][4];
#pragma unroll
            for (int j = 0; j < 8; j++)
#pragma unroll
                for (int i = 0; i < 4; i++) s[j][i] = 0.0f;

            // ---- S = (q_hi + q_lo) . K ----
#pragma unroll
            for (int kk = 0; kk < 8; kk++) {
                uint32_t qh[4], ql[4];
                ldm_x4(qh, Qb + (qrow_off + kk * 16) * 2);
                ldm_x4(ql, Qb + (qrow_off + 128 + kk * 16) * 2);
#pragma unroll
                for (int g = 0; g < 4; g++) {
                    uint32_t kb[4];
                    ldm_x4(kb, Kb + ((g * 16 + krow) * KVS + kcol + kk * 16) * 2);
                    mma16816h(s[2 * g],     qh, kb[0], kb[1]);
                    mma16816h(s[2 * g + 1], qh, kb[2], kb[3]);
                    mma16816h(s[2 * g],     ql, kb[0], kb[1]);
                    mma16816h(s[2 * g + 1], ql, kb[2], kb[3]);
                }
            }

            if (k0 + 63 > wrow) {
                const int c0 = k0 + ((lane & 3) << 1);
#pragma unroll
                for (int j = 0; j < 8; j++) {
                    int cc = c0 + j * 8;
                    if (cc     > r0g)     s[j][0] = -1e30f;
                    if (cc + 1 > r0g)     s[j][1] = -1e30f;
                    if (cc     > r0g + 8) s[j][2] = -1e30f;
                    if (cc + 1 > r0g + 8) s[j][3] = -1e30f;
                }
            }

            float mt0 = -1e30f, mt1 = -1e30f;
#pragma unroll
            for (int j = 0; j < 8; j++) {
                mt0 = fmaxf(mt0, fmaxf(s[j][0], s[j][1]));
                mt1 = fmaxf(mt1, fmaxf(s[j][2], s[j][3]));
            }
            mt0 = fmaxf(mt0, __shfl_xor_sync(0xffffffffu, mt0, 1));
            mt0 = fmaxf(mt0, __shfl_xor_sync(0xffffffffu, mt0, 2));
            mt1 = fmaxf(mt1, __shfl_xor_sync(0xffffffffu, mt1, 1));
            mt1 = fmaxf(mt1, __shfl_xor_sync(0xffffffffu, mt1, 2));
            const float mn0 = fmaxf(m0, mt0), mn1 = fmaxf(m1, mt1);
            const float corr0 = __expf(m0 - mn0), corr1 = __expf(m1 - mn1);
            m0 = mn0; m1 = mn1;
            float rs0 = 0.0f, rs1 = 0.0f;
#pragma unroll
            for (int j = 0; j < 8; j++) {
                s[j][0] = __expf(s[j][0] - mn0);
                s[j][1] = __expf(s[j][1] - mn0);
                s[j][2] = __expf(s[j][2] - mn1);
                s[j][3] = __expf(s[j][3] - mn1);
                rs0 += s[j][0] + s[j][1];
                rs1 += s[j][2] + s[j][3];
            }
            rs0 += __shfl_xor_sync(0xffffffffu, rs0, 1);
            rs0 += __shfl_xor_sync(0xffffffffu, rs0, 2);
            rs1 += __shfl_xor_sync(0xffffffffu, rs1, 1);
            rs1 += __shfl_xor_sync(0xffffffffu, rs1, 2);
            l0 = l0 * corr0 + rs0;
            l1 = l1 * corr1 + rs1;
#pragma unroll
            for (int n = 0; n < 16; n++) {
                O[n][0] *= corr0;  O[n][1] *= corr0;
                O[n][2] *= corr1;  O[n][3] *= corr1;
            }

            // ---- O += (P_hi + P_lo) . V ----
#pragma unroll
            for (int kt = 0; kt < 4; kt++) {
                uint32_t ph[4], pl[4];
                ph[0] = packh2(s[2 * kt][0], s[2 * kt][1]);
                pl[0] = packh2(s[2 * kt][0] - h2_low(ph[0]), s[2 * kt][1] - h2_high(ph[0]));
                ph[1] = packh2(s[2 * kt][2], s[2 * kt][3]);
                pl[1] = packh2(s[2 * kt][2] - h2_low(ph[1]), s[2 * kt][3] - h2_high(ph[1]));
                ph[2] = packh2(s[2 * kt + 1][0], s[2 * kt + 1][1]);
                pl[2] = packh2(s[2 * kt + 1][0] - h2_low(ph[2]), s[2 * kt + 1][1] - h2_high(ph[2]));
                ph[3] = packh2(s[2 * kt + 1][2], s[2 * kt + 1][3]);
                pl[3] = packh2(s[2 * kt + 1][2] - h2_low(ph[3]), s[2 * kt + 1][3] - h2_high(ph[3]));
#pragma unroll
                for (int g = 0; g < 8; g++) {
                    uint32_t vb[4];
                    ldm_x4_t(vb, Vb + ((kt * 16 + vrow_off) * KVS + g * 16 + vcol8) * 2);
                    mma16816h(O[2 * g],     ph, vb[0], vb[1]);
                    mma16816h(O[2 * g + 1], ph, vb[2], vb[3]);
                    mma16816h(O[2 * g],     pl, vb[0], vb[1]);
                    mma16816h(O[2 * g + 1], pl, vb[2], vb[3]);
                }
            }
        }
        __syncthreads();
    }

    // ---- normalize + store fp16 to g_a ----
    const float inv0 = 1.0f / l0, inv1 = 1.0f / l1;
    const int sr0 = wrow + (lane >> 2), sr1 = sr0 + 8;
#pragma unroll
    for (int n = 0; n < 16; n++) {
        const int d = n * 8 + ((lane & 3) << 1);
        {
            float v0 = O[n][0] * inv0, v1 = O[n][1] * inv0;
            __half* p = g_a + (size_t)sr0 * DIM + h * 128 + d;
            *reinterpret_cast<uint32_t*>(p) = packh2(v0, v1);
        }
        {
            float v2 = O[n][2] * inv1, v3 = O[n][3] * inv1;
            __half* p = g_a + (size_t)sr1 * DIM + h * 128 + d;
            *reinterpret_cast<uint32_t*>(p) = packh2(v2, v3);
        }
    }
}

// ---------------- launch -----------------------------------------------------
// inputs: 0:x 1:start_pos 2:freqs 3:mask 4:wq 5:wk 6:wv 7:wo  (mask analytic)
extern "C" void kernel_launch(void* const* d_in, const int* in_sizes, int n_in,
                              void* d_out, int out_size)
{
    const float* x     = (const float*)d_in[0];
    const float* freqs = (const float*)d_in[2];
    const float* wq    = (const float*)d_in[4];
    const float* wk    = (const float*)d_in[5];
    const float* wv    = (const float*)d_in[6];
    const float* wo    = (const float*)d_in[7];
    float* out = (float*)d_out;

    cudaFuncSetAttribute(attn_kernel,     cudaFuncAttributeMaxDynamicSharedMemorySize, ATTN_SMEM);
    cudaFuncSetAttribute(qkv_gemm_kernel, cudaFuncAttributeMaxDynamicSharedMemorySize, GEMM_SMEM);
    cudaFuncSetAttribute(out_gemm_kernel, cudaFuncAttributeMaxDynamicSharedMemorySize, GEMM_SMEM);

    convert_w_kernel<<<dim3(DIM * DIM / 4 / 256, 1, 4), 256>>>(wq, wk, wv, wo);
    convert_x_kernel<<<SEQ * DIM / 4 / 256, 256>>>(x);
    qkv_gemm_kernel<<<dim3(SEQ / 128, DIM / 128, 3), 128, GEMM_SMEM>>>(freqs);
    attn_kernel<<<dim3(SEQ / 128, NH), 256, ATTN_SMEM>>>();
    out_gemm_kernel<<<dim3(SEQ / 128, DIM / 128, 1), 128, GEMM_SMEM>>>(out);
}

// round 14
// speedup vs baseline: 2.1922x; 1.0759x over previous
#include <cuda_runtime.h>
#include <cuda_fp16.h>
#include <math.h>
#include <stdint.h>

#define SEQ 2048
#define DIM 4096
#define NH  32
#define HD  128

// ---------------- scratch (__device__ globals; no cudaMalloc allowed) -------
__device__ __half g_wh[4ull * DIM * DIM];                // weights hi, single copy
__device__ __half g_x [(size_t)SEQ * DIM];               // x  (fp16)
__device__ __half g_a [(size_t)SEQ * DIM];               // attn out (fp16)
__device__ __half g_qs[(size_t)SEQ * NH * 128];          // q per head, plain fp16
__device__ __half g_ks[(size_t)SEQ * NH * 128];          // k per head, plain fp16
__device__ __half g_vs[(size_t)SEQ * NH * 128];          // v per head, plain fp16

// ---------------- PTX helpers ----------------------------------------------
__device__ __forceinline__ uint32_t smem_u32(const void* p) {
    uint32_t a;
    asm("{ .reg .u64 t; cvta.to.shared.u64 t, %1; cvt.u32.u64 %0, t; }" : "=r"(a) : "l"(p));
    return a;
}
__device__ __forceinline__ void cp_async16(uint32_t dst, const void* src) {
    asm volatile("cp.async.cg.shared.global [%0], [%1], 16;" :: "r"(dst), "l"(src));
}
#define CP_COMMIT()  asm volatile("cp.async.commit_group;" ::: "memory")
#define CP_WAIT(n)   asm volatile("cp.async.wait_group %0;" :: "n"(n) : "memory")

__device__ __forceinline__ void ldm_x4(uint32_t* r, uint32_t addr) {
    asm volatile("ldmatrix.sync.aligned.m8n8.x4.shared.b16 {%0,%1,%2,%3}, [%4];"
        : "=r"(r[0]), "=r"(r[1]), "=r"(r[2]), "=r"(r[3]) : "r"(addr));
}
__device__ __forceinline__ void ldm_x4_t(uint32_t* r, uint32_t addr) {
    asm volatile("ldmatrix.sync.aligned.m8n8.x4.trans.shared.b16 {%0,%1,%2,%3}, [%4];"
        : "=r"(r[0]), "=r"(r[1]), "=r"(r[2]), "=r"(r[3]) : "r"(addr));
}
// fp16 mma, fp32 accum
__device__ __forceinline__ void mma16816h(float* c, const uint32_t* a, uint32_t b0, uint32_t b1) {
    asm volatile(
        "mma.sync.aligned.m16n8k16.row.col.f32.f16.f16.f32 "
        "{%0,%1,%2,%3}, {%4,%5,%6,%7}, {%8,%9}, {%0,%1,%2,%3};"
        : "+f"(c[0]), "+f"(c[1]), "+f"(c[2]), "+f"(c[3])
        : "r"(a[0]), "r"(a[1]), "r"(a[2]), "r"(a[3]), "r"(b0), "r"(b1));
}
__device__ __forceinline__ uint32_t packh2(float lo, float hi) {
    __half2 h = __floats2half2_rn(lo, hi);
    return *reinterpret_cast<uint32_t*>(&h);
}

// ---------------- converters -------------------------------------------------
// Weights: single hi copy [DIM x DIM]
__global__ __launch_bounds__(256) void convert_w_kernel(
    const float* __restrict__ w0, const float* __restrict__ w1,
    const float* __restrict__ w2, const float* __restrict__ w3)
{
    const float* w = (blockIdx.z == 0) ? w0 : (blockIdx.z == 1) ? w1 :
                     (blockIdx.z == 2) ? w2 : w3;
    __half* dst = g_wh + (size_t)blockIdx.z * DIM * DIM;
    int idx = blockIdx.x * 256 + threadIdx.x;
    float4 v = reinterpret_cast<const float4*>(w)[idx];
    __half hi[4];
    hi[0] = __float2half_rn(v.x); hi[1] = __float2half_rn(v.y);
    hi[2] = __float2half_rn(v.z); hi[3] = __float2half_rn(v.w);
    *reinterpret_cast<uint2*>(dst + (size_t)idx * 4) = *reinterpret_cast<uint2*>(hi);
}

// x: fp16
__global__ __launch_bounds__(256) void convert_x_kernel(const float* __restrict__ x)
{
    int idx = blockIdx.x * 256 + threadIdx.x;
    float4 v = reinterpret_cast<const float4*>(x)[idx];
    __half hi[4];
    hi[0] = __float2half_rn(v.x); hi[1] = __float2half_rn(v.y);
    hi[2] = __float2half_rn(v.z); hi[3] = __float2half_rn(v.w);
    *reinterpret_cast<uint2*>(g_x + (size_t)idx * 4) = *reinterpret_cast<uint2*>(hi);
}

// ---------------- HMMA fp16 GEMM: 4 warps, warp tile 64x64 ------------------
// C[128x128] = A[M,DIM] . B[N,DIM]^T, plain fp16, f32 accum.
// 128 threads, 4 warps (2m x 2n), BK=32, 3-stage cp.async.
#define BK 32
#define NKSTEP (DIM / BK)    // 128
#define ASTR 40
#define GSTAGES 3
#define GEMM_SMEM (GSTAGES * 2 * 128 * ASTR * (int)sizeof(__half))  // 61440

__device__ __forceinline__ void hgemm_body(
    const __half* __restrict__ A,          // [M x DIM]
    const __half* __restrict__ B,          // [4096 x 4096]
    float* __restrict__ C,                 // omode 0
    __half* __restrict__ hdst,             // omode 1: per-head fp16 [SEQ][NH][128]
    int omode,
    const float* __restrict__ freqs, int rope, float qsc,
    int m0, int n0)
{
    extern __shared__ __half gsm[];
    __half* sA = gsm;                          // GSTAGES x 128 x ASTR
    __half* sB = gsm + GSTAGES * 128 * ASTR;   // GSTAGES x 128 x ASTR

    const int tid  = threadIdx.x;
    const int wid  = tid >> 5;
    const int lane = tid & 31;
    const int wm   = wid >> 1;   // 0..1 -> rows wm*64
    const int wn   = wid & 1;    // 0..1 -> cols wn*64

    float acc[4][8][4];
#pragma unroll
    for (int mi = 0; mi < 4; mi++)
#pragma unroll
        for (int ni = 0; ni < 8; ni++)
#pragma unroll
            for (int j = 0; j < 4; j++) acc[mi][ni][j] = 0.0f;

    const __half* agp = A + (size_t)m0 * DIM;
    const __half* bgp = B + (size_t)n0 * DIM;

    auto load_tile = [&](int kstep, int s) {
        const size_t ka = (size_t)kstep * BK;
#pragma unroll
        for (int l = 0; l < 4; l++) {
            int i = tid + l * 128;
            int r = i >> 2, seg = i & 3;
            cp_async16(smem_u32(sA + (s * 128 + r) * ASTR + seg * 8), agp + (size_t)r * DIM + ka + seg * 8);
            cp_async16(smem_u32(sB + (s * 128 + r) * ASTR + seg * 8), bgp + (size_t)r * DIM + ka + seg * 8);
        }
        CP_COMMIT();
    };

    load_tile(0, 0);
    load_tile(1, 1);

    for (int k = 0; k < NKSTEP; k++) {
        if (k + 1 < NKSTEP) { CP_WAIT(1); } else { CP_WAIT(0); }
        __syncthreads();
        if (k + 2 < NKSTEP) load_tile(k + 2, (k + 2) % GSTAGES);

        const int s = k % GSTAGES;
#pragma unroll
        for (int kk = 0; kk < 2; kk++) {
            const int k0 = kk * 16;
            uint32_t af[4][4], bf[8][2];
#pragma unroll
            for (int mi = 0; mi < 4; mi++) {
                int row = wm * 64 + mi * 16 + (lane & 15);
                ldm_x4(af[mi], smem_u32(sA + (s * 128 + row) * ASTR + k0 + ((lane >> 4) << 3)));
            }
#pragma unroll
            for (int np = 0; np < 4; np++) {
                int rown = wn * 64 + np * 16 + ((lane >> 4) << 3) + (lane & 7);
                uint32_t b[4];
                ldm_x4(b, smem_u32(sB + (s * 128 + rown) * ASTR + k0 + (((lane >> 3) & 1) << 3)));
                bf[2 * np][0] = b[0];  bf[2 * np][1] = b[1];
                bf[2 * np + 1][0] = b[2];  bf[2 * np + 1][1] = b[3];
            }
#pragma unroll
            for (int mi = 0; mi < 4; mi++)
#pragma unroll
                for (int ni = 0; ni < 8; ni++)
                    mma16816h(acc[mi][ni], af[mi], bf[ni][0], bf[ni][1]);
        }
    }

#pragma unroll
    for (int mi = 0; mi < 4; mi++) {
        const int ra = m0 + wm * 64 + mi * 16 + (lane >> 2);
        const int rb = ra + 8;
#pragma unroll
        for (int ni = 0; ni < 8; ni++) {
            const int col = n0 + wn * 64 + ni * 8 + ((lane & 3) << 1);
            float d0 = acc[mi][ni][0], d1 = acc[mi][ni][1];
            float d2 = acc[mi][ni][2], d3 = acc[mi][ni][3];
            if (rope) {
                const int hd = col & (HD - 1);          // even
                float ca = freqs[ra * HD + hd], sa = freqs[ra * HD + hd + 1];
                float cb = freqs[rb * HD + hd], sb = freqs[rb * HD + hd + 1];
                d0 *= (ca - sa) * qsc;  d1 *= (ca + sa) * qsc;
                d2 *= (cb - sb) * qsc;  d3 *= (cb + sb) * qsc;
            }
            if (omode == 1) {                       // q/k/v: per-head plain fp16
                const int head = col >> 7, d = col & 127;
                *reinterpret_cast<uint32_t*>(hdst + ((size_t)ra * NH + head) * 128 + d) = packh2(d0, d1);
                *reinterpret_cast<uint32_t*>(hdst + ((size_t)rb * NH + head) * 128 + d) = packh2(d2, d3);
            } else {
                *reinterpret_cast<float2*>(&C[(size_t)ra * DIM + col]) = make_float2(d0, d1);
                *reinterpret_cast<float2*>(&C[(size_t)rb * DIM + col]) = make_float2(d2, d3);
            }
        }
    }
}

__global__ __launch_bounds__(128, 2) void qkv_gemm_kernel(const float* __restrict__ freqs)
{
    const int z = blockIdx.z;
    const __half* B = g_wh + (size_t)z * DIM * DIM;
    __half* dst = (z == 0) ? g_qs : (z == 1) ? g_ks : g_vs;
    const float qsc = (z == 0) ? 0.08838834764831845f : 1.0f;
    hgemm_body(g_x, B, nullptr, dst, 1, freqs, (z < 2) ? 1 : 0, qsc,
               blockIdx.x * 128, blockIdx.y * 128);
}

__global__ __launch_bounds__(128, 2) void out_gemm_kernel(float* __restrict__ out)
{
    hgemm_body(g_a, g_wh + 3ull * DIM * DIM, out, nullptr, 0, nullptr, 0, 1.0f,
               blockIdx.x * 128, blockIdx.y * 128);
}

// ---------------- fp16 flash attention (single-term, heavy-tiles-first) -----
// CTA: 128 q x 64 kv, 8 warps. q, K, V plain fp16.
// S = q.K ; O += P.V
#define KVS 136                       // smem row stride (128 + 8)
#define ATTN_SMEM ((128 * KVS + 4 * 64 * KVS) * (int)sizeof(__half))  // 104448

__global__ __launch_bounds__(256, 1) void attn_kernel()
{
    extern __shared__ __half sm_attn[];
    __half* sQ = sm_attn;                  // 128 x KVS
    __half* sK = sQ + 128 * KVS;           // 2 x 64 x KVS
    __half* sV = sK + 2 * 64 * KVS;        // 2 x 64 x KVS

    const int h   = blockIdx.y;
    const int q0  = (gridDim.x - 1 - blockIdx.x) * 128;   // heavy tiles first
    const int tid = threadIdx.x;
    const int wid = tid >> 5, lane = tid & 31;

    for (int i = tid; i < 128 * 16; i += 256) {
        int r = i >> 4, c = i & 15;
        cp_async16(smem_u32(sQ + r * KVS) + c * 16,
                   g_qs + ((size_t)(q0 + r) * NH + h) * 128 + c * 8);
    }
    CP_COMMIT();

    const int nt = q0 / 64 + 2;

    auto load_kv = [&](int t, int s) {
        for (int i = tid; i < 64 * 16 * 2; i += 256) {
            int half_sel = i >= 64 * 16;
            int j = i & (64 * 16 - 1);
            int r = j >> 4, c = j & 15;
            size_t src = ((size_t)(t * 64 + r) * NH + h) * 128 + c * 8;
            __half* dst = (half_sel ? sV : sK) + (s * 64 + r) * KVS + c * 8;
            cp_async16(smem_u32(dst), (half_sel ? g_vs : g_ks) + src);
        }
        CP_COMMIT();
    };
    load_kv(0, 0);

    float m0 = -1e30f, m1 = -1e30f, l0 = 0.0f, l1 = 0.0f;
    float O[16][4];
#pragma unroll
    for (int n = 0; n < 16; n++)
#pragma unroll
        for (int j = 0; j < 4; j++) O[n][j] = 0.0f;

    const int wrow = q0 + wid * 16;
    const int r0g  = wrow + (lane >> 2);
    const uint32_t Qb = smem_u32(sQ);
    const uint32_t qrow_off = (uint32_t)((wid * 16 + (lane & 15)) * KVS + ((lane >> 4) << 3));
    const uint32_t krow = (uint32_t)(((lane >> 4) << 3) + (lane & 7));
    const uint32_t kcol = (uint32_t)(((lane >> 3) & 1) << 3);
    const uint32_t vrow_off = (uint32_t)(lane & 15);
    const uint32_t vcol8 = (uint32_t)((lane >> 4) << 3);

    for (int t = 0; t < nt; t++) {
        if (t + 1 < nt) { load_kv(t + 1, (t + 1) & 1); CP_WAIT(1); }
        else           { CP_WAIT(0); }
        __syncthreads();
        const int k0 = t * 64;

        if (k0 <= wrow + 15) {
            const uint32_t Kb = smem_u32(sK + (t & 1) * 64 * KVS);
            const uint32_t Vb = smem_u32(sV + (t & 1) * 64 * KVS);

            float s[8][4];
#pragma unroll
            for (int j = 0; j < 8; j++)
#pragma unroll
                for (int i = 0; i < 4; i++) s[j][i] = 0.0f;

            // ---- S = q . K ----
#pragma unroll
            for (int kk = 0; kk < 8; kk++) {
                uint32_t qh[4];
                ldm_x4(qh, Qb + (qrow_off + kk * 16) * 2);
#pragma unroll
                for (int g = 0; g < 4; g++) {
                    uint32_t kb[4];
                    ldm_x4(kb, Kb + ((g * 16 + krow) * KVS + kcol + kk * 16) * 2);
                    mma16816h(s[2 * g],     qh, kb[0], kb[1]);
                    mma16816h(s[2 * g + 1], qh, kb[2], kb[3]);
                }
            }

            if (k0 + 63 > wrow) {
                const int c0 = k0 + ((lane & 3) << 1);
#pragma unroll
                for (int j = 0; j < 8; j++) {
                    int cc = c0 + j * 8;
                    if (cc     > r0g)     s[j][0] = -1e30f;
                    if (cc + 1 > r0g)     s[j][1] = -1e30f;
                    if (cc     > r0g + 8) s[j][2] = -1e30f;
                    if (cc + 1 > r0g + 8) s[j][3] = -1e30f;
                }
            }

            float mt0 = -1e30f, mt1 = -1e30f;
#pragma unroll
            for (int j = 0; j < 8; j++) {
                mt0 = fmaxf(mt0, fmaxf(s[j][0], s[j][1]));
                mt1 = fmaxf(mt1, fmaxf(s[j][2], s[j][3]));
            }
            mt0 = fmaxf(mt0, __shfl_xor_sync(0xffffffffu, mt0, 1));
            mt0 = fmaxf(mt0, __shfl_xor_sync(0xffffffffu, mt0, 2));
            mt1 = fmaxf(mt1, __shfl_xor_sync(0xffffffffu, mt1, 1));
            mt1 = fmaxf(mt1, __shfl_xor_sync(0xffffffffu, mt1, 2));
            const float mn0 = fmaxf(m0, mt0), mn1 = fmaxf(m1, mt1);
            const float corr0 = __expf(m0 - mn0), corr1 = __expf(m1 - mn1);
            m0 = mn0; m1 = mn1;
            float rs0 = 0.0f, rs1 = 0.0f;
#pragma unroll
            for (int j = 0; j < 8; j++) {
                s[j][0] = __expf(s[j][0] - mn0);
                s[j][1] = __expf(s[j][1] - mn0);
                s[j][2] = __expf(s[j][2] - mn1);
                s[j][3] = __expf(s[j][3] - mn1);
                rs0 += s[j][0] + s[j][1];
                rs1 += s[j][2] + s[j][3];
            }
            rs0 += __shfl_xor_sync(0xffffffffu, rs0, 1);
            rs0 += __shfl_xor_sync(0xffffffffu, rs0, 2);
            rs1 += __shfl_xor_sync(0xffffffffu, rs1, 1);
            rs1 += __shfl_xor_sync(0xffffffffu, rs1, 2);
            l0 = l0 * corr0 + rs0;
            l1 = l1 * corr1 + rs1;
#pragma unroll
            for (int n = 0; n < 16; n++) {
                O[n][0] *= corr0;  O[n][1] *= corr0;
                O[n][2] *= corr1;  O[n][3] *= corr1;
            }

            // ---- O += P . V ----
#pragma unroll
            for (int kt = 0; kt < 4; kt++) {
                uint32_t ph[4];
                ph[0] = packh2(s[2 * kt][0],     s[2 * kt][1]);
                ph[1] = packh2(s[2 * kt][2],     s[2 * kt][3]);
                ph[2] = packh2(s[2 * kt + 1][0], s[2 * kt + 1][1]);
                ph[3] = packh2(s[2 * kt + 1][2], s[2 * kt + 1][3]);
#pragma unroll
                for (int g = 0; g < 8; g++) {
                    uint32_t vb[4];
                    ldm_x4_t(vb, Vb + ((kt * 16 + vrow_off) * KVS + g * 16 + vcol8) * 2);
                    mma16816h(O[2 * g],     ph, vb[0], vb[1]);
                    mma16816h(O[2 * g + 1], ph, vb[2], vb[3]);
                }
            }
        }
        __syncthreads();
    }

    // ---- normalize + store fp16 to g_a ----
    const float inv0 = 1.0f / l0, inv1 = 1.0f / l1;
    const int sr0 = wrow + (lane >> 2), sr1 = sr0 + 8;
#pragma unroll
    for (int n = 0; n < 16; n++) {
        const int d = n * 8 + ((lane & 3) << 1);
        {
            float v0 = O[n][0] * inv0, v1 = O[n][1] * inv0;
            __half* p = g_a + (size_t)sr0 * DIM + h * 128 + d;
            *reinterpret_cast<uint32_t*>(p) = packh2(v0, v1);
        }
        {
            float v2 = O[n][2] * inv1, v3 = O[n][3] * inv1;
            __half* p = g_a + (size_t)sr1 * DIM + h * 128 + d;
            *reinterpret_cast<uint32_t*>(p) = packh2(v2, v3);
        }
    }
}

// ---------------- launch -----------------------------------------------------
// inputs: 0:x 1:start_pos 2:freqs 3:mask 4:wq 5:wk 6:wv 7:wo  (mask analytic)
extern "C" void kernel_launch(void* const* d_in, const int* in_sizes, int n_in,
                              void* d_out, int out_size)
{
    const float* x     = (const float*)d_in[0];
    const float* freqs = (const float*)d_in[2];
    const float* wq    = (const float*)d_in[4];
    const float* wk    = (const float*)d_in[5];
    const float* wv    = (const float*)d_in[6];
    const float* wo    = (const float*)d_in[7];
    float* out = (float*)d_out;

    cudaFuncSetAttribute(attn_kernel,     cudaFuncAttributeMaxDynamicSharedMemorySize, ATTN_SMEM);
    cudaFuncSetAttribute(qkv_gemm_kernel, cudaFuncAttributeMaxDynamicSharedMemorySize, GEMM_SMEM);
    cudaFuncSetAttribute(out_gemm_kernel, cudaFuncAttributeMaxDynamicSharedMemorySize, GEMM_SMEM);

    convert_w_kernel<<<dim3(DIM * DIM / 4 / 256, 1, 4), 256>>>(wq, wk, wv, wo);
    convert_x_kernel<<<SEQ * DIM / 4 / 256, 256>>>(x);
    qkv_gemm_kernel<<<dim3(SEQ / 128, DIM / 128, 3), 128, GEMM_SMEM>>>(freqs);
    attn_kernel<<<dim3(SEQ / 128, NH), 256, ATTN_SMEM>>>();
    out_gemm_kernel<<<dim3(SEQ / 128, DIM / 128, 1), 128, GEMM_SMEM>>>(out);
}

// round 15
// speedup vs baseline: 2.2231x; 1.0141x over previous
#include <cuda_runtime.h>
#include <cuda_fp16.h>
#include <math.h>
#include <stdint.h>

#define SEQ 2048
#define DIM 4096
#define NH  32
#define HD  128

// ---------------- scratch (__device__ globals; no cudaMalloc allowed) -------
__device__ __half g_wh[4ull * DIM * DIM];                // weights, fp16
__device__ __half g_x [(size_t)SEQ * DIM];               // x  (fp16)
__device__ __half g_a [(size_t)SEQ * DIM];               // attn out (fp16)
__device__ __half g_qs[(size_t)SEQ * NH * 128];          // q per head, fp16
__device__ __half g_ks[(size_t)SEQ * NH * 128];          // k per head, fp16
__device__ __half g_vs[(size_t)SEQ * NH * 128];          // v per head, fp16

// ---------------- PTX helpers ----------------------------------------------
__device__ __forceinline__ uint32_t smem_u32(const void* p) {
    uint32_t a;
    asm("{ .reg .u64 t; cvta.to.shared.u64 t, %1; cvt.u32.u64 %0, t; }" : "=r"(a) : "l"(p));
    return a;
}
__device__ __forceinline__ void cp_async16(uint32_t dst, const void* src) {
    asm volatile("cp.async.cg.shared.global [%0], [%1], 16;" :: "r"(dst), "l"(src));
}
#define CP_COMMIT()  asm volatile("cp.async.commit_group;" ::: "memory")
#define CP_WAIT(n)   asm volatile("cp.async.wait_group %0;" :: "n"(n) : "memory")

__device__ __forceinline__ void ldm_x4(uint32_t* r, uint32_t addr) {
    asm volatile("ldmatrix.sync.aligned.m8n8.x4.shared.b16 {%0,%1,%2,%3}, [%4];"
        : "=r"(r[0]), "=r"(r[1]), "=r"(r[2]), "=r"(r[3]) : "r"(addr));
}
__device__ __forceinline__ void ldm_x4_t(uint32_t* r, uint32_t addr) {
    asm volatile("ldmatrix.sync.aligned.m8n8.x4.trans.shared.b16 {%0,%1,%2,%3}, [%4];"
        : "=r"(r[0]), "=r"(r[1]), "=r"(r[2]), "=r"(r[3]) : "r"(addr));
}
// fp16 mma, fp32 accum
__device__ __forceinline__ void mma16816h(float* c, const uint32_t* a, uint32_t b0, uint32_t b1) {
    asm volatile(
        "mma.sync.aligned.m16n8k16.row.col.f32.f16.f16.f32 "
        "{%0,%1,%2,%3}, {%4,%5,%6,%7}, {%8,%9}, {%0,%1,%2,%3};"
        : "+f"(c[0]), "+f"(c[1]), "+f"(c[2]), "+f"(c[3])
        : "r"(a[0]), "r"(a[1]), "r"(a[2]), "r"(a[3]), "r"(b0), "r"(b1));
}
__device__ __forceinline__ uint32_t packh2(float lo, float hi) {
    __half2 h = __floats2half2_rn(lo, hi);
    return *reinterpret_cast<uint32_t*>(&h);
}

// ---------------- converters -------------------------------------------------
__global__ __launch_bounds__(256) void convert_w_kernel(
    const float* __restrict__ w0, const float* __restrict__ w1,
    const float* __restrict__ w2, const float* __restrict__ w3)
{
    const float* w = (blockIdx.z == 0) ? w0 : (blockIdx.z == 1) ? w1 :
                     (blockIdx.z == 2) ? w2 : w3;
    __half* dst = g_wh + (size_t)blockIdx.z * DIM * DIM;
    int idx = blockIdx.x * 256 + threadIdx.x;
    float4 v = reinterpret_cast<const float4*>(w)[idx];
    __half hi[4];
    hi[0] = __float2half_rn(v.x); hi[1] = __float2half_rn(v.y);
    hi[2] = __float2half_rn(v.z); hi[3] = __float2half_rn(v.w);
    *reinterpret_cast<uint2*>(dst + (size_t)idx * 4) = *reinterpret_cast<uint2*>(hi);
}

__global__ __launch_bounds__(256) void convert_x_kernel(const float* __restrict__ x)
{
    int idx = blockIdx.x * 256 + threadIdx.x;
    float4 v = reinterpret_cast<const float4*>(x)[idx];
    __half hi[4];
    hi[0] = __float2half_rn(v.x); hi[1] = __float2half_rn(v.y);
    hi[2] = __float2half_rn(v.z); hi[3] = __float2half_rn(v.w);
    *reinterpret_cast<uint2*>(g_x + (size_t)idx * 4) = *reinterpret_cast<uint2*>(hi);
}

// ---------------- HMMA fp16 GEMM: 4 warps, warp tile 64x64 (R14) ------------
#define BK 32
#define NKSTEP (DIM / BK)    // 128
#define ASTR 40
#define GSTAGES 3
#define GEMM_SMEM (GSTAGES * 2 * 128 * ASTR * (int)sizeof(__half))  // 61440

__device__ __forceinline__ void hgemm_body(
    const __half* __restrict__ A,
    const __half* __restrict__ B,
    float* __restrict__ C,                 // omode 0
    __half* __restrict__ hdst,             // omode 1: per-head fp16
    int omode,
    const float* __restrict__ freqs, int rope, float qsc,
    int m0, int n0)
{
    extern __shared__ __half gsm[];
    __half* sA = gsm;
    __half* sB = gsm + GSTAGES * 128 * ASTR;

    const int tid  = threadIdx.x;
    const int wid  = tid >> 5;
    const int lane = tid & 31;
    const int wm   = wid >> 1;
    const int wn   = wid & 1;

    float acc[4][8][4];
#pragma unroll
    for (int mi = 0; mi < 4; mi++)
#pragma unroll
        for (int ni = 0; ni < 8; ni++)
#pragma unroll
            for (int j = 0; j < 4; j++) acc[mi][ni][j] = 0.0f;

    const __half* agp = A + (size_t)m0 * DIM;
    const __half* bgp = B + (size_t)n0 * DIM;

    auto load_tile = [&](int kstep, int s) {
        const size_t ka = (size_t)kstep * BK;
#pragma unroll
        for (int l = 0; l < 4; l++) {
            int i = tid + l * 128;
            int r = i >> 2, seg = i & 3;
            cp_async16(smem_u32(sA + (s * 128 + r) * ASTR + seg * 8), agp + (size_t)r * DIM + ka + seg * 8);
            cp_async16(smem_u32(sB + (s * 128 + r) * ASTR + seg * 8), bgp + (size_t)r * DIM + ka + seg * 8);
        }
        CP_COMMIT();
    };

    load_tile(0, 0);
    load_tile(1, 1);

    for (int k = 0; k < NKSTEP; k++) {
        if (k + 1 < NKSTEP) { CP_WAIT(1); } else { CP_WAIT(0); }
        __syncthreads();
        if (k + 2 < NKSTEP) load_tile(k + 2, (k + 2) % GSTAGES);

        const int s = k % GSTAGES;
#pragma unroll
        for (int kk = 0; kk < 2; kk++) {
            const int k0 = kk * 16;
            uint32_t af[4][4], bf[8][2];
#pragma unroll
            for (int mi = 0; mi < 4; mi++) {
                int row = wm * 64 + mi * 16 + (lane & 15);
                ldm_x4(af[mi], smem_u32(sA + (s * 128 + row) * ASTR + k0 + ((lane >> 4) << 3)));
            }
#pragma unroll
            for (int np = 0; np < 4; np++) {
                int rown = wn * 64 + np * 16 + ((lane >> 4) << 3) + (lane & 7);
                uint32_t b[4];
                ldm_x4(b, smem_u32(sB + (s * 128 + rown) * ASTR + k0 + (((lane >> 3) & 1) << 3)));
                bf[2 * np][0] = b[0];  bf[2 * np][1] = b[1];
                bf[2 * np + 1][0] = b[2];  bf[2 * np + 1][1] = b[3];
            }
#pragma unroll
            for (int mi = 0; mi < 4; mi++)
#pragma unroll
                for (int ni = 0; ni < 8; ni++)
                    mma16816h(acc[mi][ni], af[mi], bf[ni][0], bf[ni][1]);
        }
    }

#pragma unroll
    for (int mi = 0; mi < 4; mi++) {
        const int ra = m0 + wm * 64 + mi * 16 + (lane >> 2);
        const int rb = ra + 8;
#pragma unroll
        for (int ni = 0; ni < 8; ni++) {
            const int col = n0 + wn * 64 + ni * 8 + ((lane & 3) << 1);
            float d0 = acc[mi][ni][0], d1 = acc[mi][ni][1];
            float d2 = acc[mi][ni][2], d3 = acc[mi][ni][3];
            if (rope) {
                const int hd = col & (HD - 1);
                float ca = freqs[ra * HD + hd], sa = freqs[ra * HD + hd + 1];
                float cb = freqs[rb * HD + hd], sb = freqs[rb * HD + hd + 1];
                d0 *= (ca - sa) * qsc;  d1 *= (ca + sa) * qsc;
                d2 *= (cb - sb) * qsc;  d3 *= (cb + sb) * qsc;
            }
            if (omode == 1) {
                const int head = col >> 7, d = col & 127;
                *reinterpret_cast<uint32_t*>(hdst + ((size_t)ra * NH + head) * 128 + d) = packh2(d0, d1);
                *reinterpret_cast<uint32_t*>(hdst + ((size_t)rb * NH + head) * 128 + d) = packh2(d2, d3);
            } else {
                *reinterpret_cast<float2*>(&C[(size_t)ra * DIM + col]) = make_float2(d0, d1);
                *reinterpret_cast<float2*>(&C[(size_t)rb * DIM + col]) = make_float2(d2, d3);
            }
        }
    }
}

__global__ __launch_bounds__(128, 2) void qkv_gemm_kernel(const float* __restrict__ freqs)
{
    const int z = blockIdx.z;
    const __half* B = g_wh + (size_t)z * DIM * DIM;
    __half* dst = (z == 0) ? g_qs : (z == 1) ? g_ks : g_vs;
    const float qsc = (z == 0) ? 0.08838834764831845f : 1.0f;
    hgemm_body(g_x, B, nullptr, dst, 1, freqs, (z < 2) ? 1 : 0, qsc,
               blockIdx.x * 128, blockIdx.y * 128);
}

__global__ __launch_bounds__(128, 2) void out_gemm_kernel(float* __restrict__ out)
{
    hgemm_body(g_a, g_wh + 3ull * DIM * DIM, out, nullptr, 0, nullptr, 0, 1.0f,
               blockIdx.x * 128, blockIdx.y * 128);
}

// ---------------- fp16 flash attention: 64-q CTAs, 2 CTAs/SM ----------------
// CTA: 64 q x 64 kv, 4 warps (16 q rows each). q, K, V plain fp16.
#define KVS 136                       // smem row stride (128 + 8)
#define ATTN_SMEM ((64 * KVS + 4 * 64 * KVS) * (int)sizeof(__half))  // 87040

__global__ __launch_bounds__(128, 2) void attn_kernel()
{
    extern __shared__ __half sm_attn[];
    __half* sQ = sm_attn;                  // 64 x KVS
    __half* sK = sQ + 64 * KVS;            // 2 x 64 x KVS
    __half* sV = sK + 2 * 64 * KVS;        // 2 x 64 x KVS

    const int h   = blockIdx.y;
    const int q0  = (gridDim.x - 1 - blockIdx.x) * 64;    // heavy tiles first
    const int tid = threadIdx.x;
    const int wid = tid >> 5, lane = tid & 31;

    for (int i = tid; i < 64 * 16; i += 128) {
        int r = i >> 4, c = i & 15;
        cp_async16(smem_u32(sQ + r * KVS) + c * 16,
                   g_qs + ((size_t)(q0 + r) * NH + h) * 128 + c * 8);
    }
    CP_COMMIT();

    const int nt = q0 / 64 + 1;

    auto load_kv = [&](int t, int s) {
        for (int i = tid; i < 64 * 16 * 2; i += 128) {
            int half_sel = i >= 64 * 16;
            int j = i & (64 * 16 - 1);
            int r = j >> 4, c = j & 15;
            size_t src = ((size_t)(t * 64 + r) * NH + h) * 128 + c * 8;
            __half* dst = (half_sel ? sV : sK) + (s * 64 + r) * KVS + c * 8;
            cp_async16(smem_u32(dst), (half_sel ? g_vs : g_ks) + src);
        }
        CP_COMMIT();
    };
    load_kv(0, 0);

    float m0 = -1e30f, m1 = -1e30f, l0 = 0.0f, l1 = 0.0f;
    float O[16][4];
#pragma unroll
    for (int n = 0; n < 16; n++)
#pragma unroll
        for (int j = 0; j < 4; j++) O[n][j] = 0.0f;

    const int wrow = q0 + wid * 16;
    const int r0g  = wrow + (lane >> 2);
    const uint32_t Qb = smem_u32(sQ);
    const uint32_t qrow_off = (uint32_t)((wid * 16 + (lane & 15)) * KVS + ((lane >> 4) << 3));
    const uint32_t krow = (uint32_t)(((lane >> 4) << 3) + (lane & 7));
    const uint32_t kcol = (uint32_t)(((lane >> 3) & 1) << 3);
    const uint32_t vrow_off = (uint32_t)(lane & 15);
    const uint32_t vcol8 = (uint32_t)((lane >> 4) << 3);

    for (int t = 0; t < nt; t++) {
        if (t + 1 < nt) { load_kv(t + 1, (t + 1) & 1); CP_WAIT(1); }
        else           { CP_WAIT(0); }
        __syncthreads();
        const int k0 = t * 64;

        {
            const uint32_t Kb = smem_u32(sK + (t & 1) * 64 * KVS);
            const uint32_t Vb = smem_u32(sV + (t & 1) * 64 * KVS);

            float s[8][4];
#pragma unroll
            for (int j = 0; j < 8; j++)
#pragma unroll
                for (int i = 0; i < 4; i++) s[j][i] = 0.0f;

            // ---- S = q . K ----
#pragma unroll
            for (int kk = 0; kk < 8; kk++) {
                uint32_t qh[4];
                ldm_x4(qh, Qb + (qrow_off + kk * 16) * 2);
#pragma unroll
                for (int g = 0; g < 4; g++) {
                    uint32_t kb[4];
                    ldm_x4(kb, Kb + ((g * 16 + krow) * KVS + kcol + kk * 16) * 2);
                    mma16816h(s[2 * g],     qh, kb[0], kb[1]);
                    mma16816h(s[2 * g + 1], qh, kb[2], kb[3]);
                }
            }

            if (k0 + 63 > wrow) {
                const int c0 = k0 + ((lane & 3) << 1);
#pragma unroll
                for (int j = 0; j < 8; j++) {
                    int cc = c0 + j * 8;
                    if (cc     > r0g)     s[j][0] = -1e30f;
                    if (cc + 1 > r0g)     s[j][1] = -1e30f;
                    if (cc     > r0g + 8) s[j][2] = -1e30f;
                    if (cc + 1 > r0g + 8) s[j][3] = -1e30f;
                }
            }

            float mt0 = -1e30f, mt1 = -1e30f;
#pragma unroll
            for (int j = 0; j < 8; j++) {
                mt0 = fmaxf(mt0, fmaxf(s[j][0], s[j][1]));
                mt1 = fmaxf(mt1, fmaxf(s[j][2], s[j][3]));
            }
            mt0 = fmaxf(mt0, __shfl_xor_sync(0xffffffffu, mt0, 1));
            mt0 = fmaxf(mt0, __shfl_xor_sync(0xffffffffu, mt0, 2));
            mt1 = fmaxf(mt1, __shfl_xor_sync(0xffffffffu, mt1, 1));
            mt1 = fmaxf(mt1, __shfl_xor_sync(0xffffffffu, mt1, 2));
            const float mn0 = fmaxf(m0, mt0), mn1 = fmaxf(m1, mt1);
            const float corr0 = __expf(m0 - mn0), corr1 = __expf(m1 - mn1);
            m0 = mn0; m1 = mn1;
            float rs0 = 0.0f, rs1 = 0.0f;
#pragma unroll
            for (int j = 0; j < 8; j++) {
                s[j][0] = __expf(s[j][0] - mn0);
                s[j][1] = __expf(s[j][1] - mn0);
                s[j][2] = __expf(s[j][2] - mn1);
                s[j][3] = __expf(s[j][3] - mn1);
                rs0 += s[j][0] + s[j][1];
                rs1 += s[j][2] + s[j][3];
            }
            rs0 += __shfl_xor_sync(0xffffffffu, rs0, 1);
            rs0 += __shfl_xor_sync(0xffffffffu, rs0, 2);
            rs1 += __shfl_xor_sync(0xffffffffu, rs1, 1);
            rs1 += __shfl_xor_sync(0xffffffffu, rs1, 2);
            l0 = l0 * corr0 + rs0;
            l1 = l1 * corr1 + rs1;
#pragma unroll
            for (int n = 0; n < 16; n++) {
                O[n][0] *= corr0;  O[n][1] *= corr0;
                O[n][2] *= corr1;  O[n][3] *= corr1;
            }

            // ---- O += P . V ----
#pragma unroll
            for (int kt = 0; kt < 4; kt++) {
                uint32_t ph[4];
                ph[0] = packh2(s[2 * kt][0],     s[2 * kt][1]);
                ph[1] = packh2(s[2 * kt][2],     s[2 * kt][3]);
                ph[2] = packh2(s[2 * kt + 1][0], s[2 * kt + 1][1]);
                ph[3] = packh2(s[2 * kt + 1][2], s[2 * kt + 1][3]);
#pragma unroll
                for (int g = 0; g < 8; g++) {
                    uint32_t vb[4];
                    ldm_x4_t(vb, Vb + ((kt * 16 + vrow_off) * KVS + g * 16 + vcol8) * 2);
                    mma16816h(O[2 * g],     ph, vb[0], vb[1]);
                    mma16816h(O[2 * g + 1], ph, vb[2], vb[3]);
                }
            }
        }
        __syncthreads();
    }

    // ---- normalize + store fp16 to g_a ----
    const float inv0 = 1.0f / l0, inv1 = 1.0f / l1;
    const int sr0 = wrow + (lane >> 2), sr1 = sr0 + 8;
#pragma unroll
    for (int n = 0; n < 16; n++) {
        const int d = n * 8 + ((lane & 3) << 1);
        {
            float v0 = O[n][0] * inv0, v1 = O[n][1] * inv0;
            __half* p = g_a + (size_t)sr0 * DIM + h * 128 + d;
            *reinterpret_cast<uint32_t*>(p) = packh2(v0, v1);
        }
        {
            float v2 = O[n][2] * inv1, v3 = O[n][3] * inv1;
            __half* p = g_a + (size_t)sr1 * DIM + h * 128 + d;
            *reinterpret_cast<uint32_t*>(p) = packh2(v2, v3);
        }
    }
}

// ---------------- launch -----------------------------------------------------
// inputs: 0:x 1:start_pos 2:freqs 3:mask 4:wq 5:wk 6:wv 7:wo  (mask analytic)
extern "C" void kernel_launch(void* const* d_in, const int* in_sizes, int n_in,
                              void* d_out, int out_size)
{
    const float* x     = (const float*)d_in[0];
    const float* freqs = (const float*)d_in[2];
    const float* wq    = (const float*)d_in[4];
    const float* wk    = (const float*)d_in[5];
    const float* wv    = (const float*)d_in[6];
    const float* wo    = (const float*)d_in[7];
    float* out = (float*)d_out;

    cudaFuncSetAttribute(attn_kernel,     cudaFuncAttributeMaxDynamicSharedMemorySize, ATTN_SMEM);
    cudaFuncSetAttribute(qkv_gemm_kernel, cudaFuncAttributeMaxDynamicSharedMemorySize, GEMM_SMEM);
    cudaFuncSetAttribute(out_gemm_kernel, cudaFuncAttributeMaxDynamicSharedMemorySize, GEMM_SMEM);

    convert_w_kernel<<<dim3(DIM * DIM / 4 / 256, 1, 4), 256>>>(wq, wk, wv, wo);
    convert_x_kernel<<<SEQ * DIM / 4 / 256, 256>>>(x);
    qkv_gemm_kernel<<<dim3(SEQ / 128, DIM / 128, 3), 128, GEMM_SMEM>>>(freqs);
    attn_kernel<<<dim3(SEQ / 64, NH), 128, ATTN_SMEM>>>();
    out_gemm_kernel<<<dim3(SEQ / 128, DIM / 128, 1), 128, GEMM_SMEM>>>(out);
}

// round 16
// speedup vs baseline: 2.2290x; 1.0026x over previous
#include <cuda_runtime.h>
#include <cuda_fp16.h>
#include <math.h>
#include <stdint.h>

#define SEQ 2048
#define DIM 4096
#define NH  32
#define HD  128

// ---------------- scratch (__device__ globals; no cudaMalloc allowed) -------
__device__ __half g_wh[4ull * DIM * DIM];                // weights, fp16
__device__ __half g_x [(size_t)SEQ * DIM];               // x  (fp16)
__device__ __half g_a [(size_t)SEQ * DIM];               // attn out (fp16)
__device__ __half g_qs[(size_t)SEQ * NH * 128];          // q per head, fp16
__device__ __half g_ks[(size_t)SEQ * NH * 128];          // k per head, fp16
__device__ __half g_vs[(size_t)SEQ * NH * 128];          // v per head, fp16

// ---------------- PTX helpers ----------------------------------------------
__device__ __forceinline__ uint32_t smem_u32(const void* p) {
    uint32_t a;
    asm("{ .reg .u64 t; cvta.to.shared.u64 t, %1; cvt.u32.u64 %0, t; }" : "=r"(a) : "l"(p));
    return a;
}
__device__ __forceinline__ void cp_async16(uint32_t dst, const void* src) {
    asm volatile("cp.async.cg.shared.global [%0], [%1], 16;" :: "r"(dst), "l"(src));
}
#define CP_COMMIT()  asm volatile("cp.async.commit_group;" ::: "memory")
#define CP_WAIT(n)   asm volatile("cp.async.wait_group %0;" :: "n"(n) : "memory")

__device__ __forceinline__ void ldm_x4(uint32_t* r, uint32_t addr) {
    asm volatile("ldmatrix.sync.aligned.m8n8.x4.shared.b16 {%0,%1,%2,%3}, [%4];"
        : "=r"(r[0]), "=r"(r[1]), "=r"(r[2]), "=r"(r[3]) : "r"(addr));
}
__device__ __forceinline__ void ldm_x4_t(uint32_t* r, uint32_t addr) {
    asm volatile("ldmatrix.sync.aligned.m8n8.x4.trans.shared.b16 {%0,%1,%2,%3}, [%4];"
        : "=r"(r[0]), "=r"(r[1]), "=r"(r[2]), "=r"(r[3]) : "r"(addr));
}
// fp16 mma, fp32 accum
__device__ __forceinline__ void mma16816h(float* c, const uint32_t* a, uint32_t b0, uint32_t b1) {
    asm volatile(
        "mma.sync.aligned.m16n8k16.row.col.f32.f16.f16.f32 "
        "{%0,%1,%2,%3}, {%4,%5,%6,%7}, {%8,%9}, {%0,%1,%2,%3};"
        : "+f"(c[0]), "+f"(c[1]), "+f"(c[2]), "+f"(c[3])
        : "r"(a[0]), "r"(a[1]), "r"(a[2]), "r"(a[3]), "r"(b0), "r"(b1));
}
__device__ __forceinline__ uint32_t packh2(float lo, float hi) {
    __half2 h = __floats2half2_rn(lo, hi);
    return *reinterpret_cast<uint32_t*>(&h);
}

// ---------------- converters -------------------------------------------------
__global__ __launch_bounds__(256) void convert_w_kernel(
    const float* __restrict__ w0, const float* __restrict__ w1,
    const float* __restrict__ w2, const float* __restrict__ w3)
{
    const float* w = (blockIdx.z == 0) ? w0 : (blockIdx.z == 1) ? w1 :
                     (blockIdx.z == 2) ? w2 : w3;
    __half* dst = g_wh + (size_t)blockIdx.z * DIM * DIM;
    int idx = blockIdx.x * 256 + threadIdx.x;
    float4 v = reinterpret_cast<const float4*>(w)[idx];
    __half hi[4];
    hi[0] = __float2half_rn(v.x); hi[1] = __float2half_rn(v.y);
    hi[2] = __float2half_rn(v.z); hi[3] = __float2half_rn(v.w);
    *reinterpret_cast<uint2*>(dst + (size_t)idx * 4) = *reinterpret_cast<uint2*>(hi);
}

__global__ __launch_bounds__(256) void convert_x_kernel(const float* __restrict__ x)
{
    int idx = blockIdx.x * 256 + threadIdx.x;
    float4 v = reinterpret_cast<const float4*>(x)[idx];
    __half hi[4];
    hi[0] = __float2half_rn(v.x); hi[1] = __float2half_rn(v.y);
    hi[2] = __float2half_rn(v.z); hi[3] = __float2half_rn(v.w);
    *reinterpret_cast<uint2*>(g_x + (size_t)idx * 4) = *reinterpret_cast<uint2*>(hi);
}

// ---------------- HMMA fp16 GEMM: 4 warps, warp tile 64x64 (R14) ------------
#define BK 32
#define NKSTEP (DIM / BK)    // 128
#define ASTR 40
#define GSTAGES 3
#define GEMM_SMEM (GSTAGES * 2 * 128 * ASTR * (int)sizeof(__half))  // 61440

__device__ __forceinline__ void hgemm_body(
    const __half* __restrict__ A,
    const __half* __restrict__ B,
    float* __restrict__ C,                 // omode 0
    __half* __restrict__ hdst,             // omode 1: per-head fp16
    int omode,
    const float* __restrict__ freqs, int rope, float qsc,
    int m0, int n0)
{
    extern __shared__ __half gsm[];
    __half* sA = gsm;
    __half* sB = gsm + GSTAGES * 128 * ASTR;

    const int tid  = threadIdx.x;
    const int wid  = tid >> 5;
    const int lane = tid & 31;
    const int wm   = wid >> 1;
    const int wn   = wid & 1;

    float acc[4][8][4];
#pragma unroll
    for (int mi = 0; mi < 4; mi++)
#pragma unroll
        for (int ni = 0; ni < 8; ni++)
#pragma unroll
            for (int j = 0; j < 4; j++) acc[mi][ni][j] = 0.0f;

    const __half* agp = A + (size_t)m0 * DIM;
    const __half* bgp = B + (size_t)n0 * DIM;

    auto load_tile = [&](int kstep, int s) {
        const size_t ka = (size_t)kstep * BK;
#pragma unroll
        for (int l = 0; l < 4; l++) {
            int i = tid + l * 128;
            int r = i >> 2, seg = i & 3;
            cp_async16(smem_u32(sA + (s * 128 + r) * ASTR + seg * 8), agp + (size_t)r * DIM + ka + seg * 8);
            cp_async16(smem_u32(sB + (s * 128 + r) * ASTR + seg * 8), bgp + (size_t)r * DIM + ka + seg * 8);
        }
        CP_COMMIT();
    };

    load_tile(0, 0);
    load_tile(1, 1);

    for (int k = 0; k < NKSTEP; k++) {
        if (k + 1 < NKSTEP) { CP_WAIT(1); } else { CP_WAIT(0); }
        __syncthreads();
        if (k + 2 < NKSTEP) load_tile(k + 2, (k + 2) % GSTAGES);

        const int s = k % GSTAGES;
#pragma unroll
        for (int kk = 0; kk < 2; kk++) {
            const int k0 = kk * 16;
            uint32_t af[4][4], bf[8][2];
#pragma unroll
            for (int mi = 0; mi < 4; mi++) {
                int row = wm * 64 + mi * 16 + (lane & 15);
                ldm_x4(af[mi], smem_u32(sA + (s * 128 + row) * ASTR + k0 + ((lane >> 4) << 3)));
            }
#pragma unroll
            for (int np = 0; np < 4; np++) {
                int rown = wn * 64 + np * 16 + ((lane >> 4) << 3) + (lane & 7);
                uint32_t b[4];
                ldm_x4(b, smem_u32(sB + (s * 128 + rown) * ASTR + k0 + (((lane >> 3) & 1) << 3)));
                bf[2 * np][0] = b[0];  bf[2 * np][1] = b[1];
                bf[2 * np + 1][0] = b[2];  bf[2 * np + 1][1] = b[3];
            }
#pragma unroll
            for (int mi = 0; mi < 4; mi++)
#pragma unroll
                for (int ni = 0; ni < 8; ni++)
                    mma16816h(acc[mi][ni], af[mi], bf[ni][0], bf[ni][1]);
        }
    }

#pragma unroll
    for (int mi = 0; mi < 4; mi++) {
        const int ra = m0 + wm * 64 + mi * 16 + (lane >> 2);
        const int rb = ra + 8;
#pragma unroll
        for (int ni = 0; ni < 8; ni++) {
            const int col = n0 + wn * 64 + ni * 8 + ((lane & 3) << 1);
            float d0 = acc[mi][ni][0], d1 = acc[mi][ni][1];
            float d2 = acc[mi][ni][2], d3 = acc[mi][ni][3];
            if (rope) {
                const int hd = col & (HD - 1);
                float ca = freqs[ra * HD + hd], sa = freqs[ra * HD + hd + 1];
                float cb = freqs[rb * HD + hd], sb = freqs[rb * HD + hd + 1];
                d0 *= (ca - sa) * qsc;  d1 *= (ca + sa) * qsc;
                d2 *= (cb - sb) * qsc;  d3 *= (cb + sb) * qsc;
            }
            if (omode == 1) {
                const int head = col >> 7, d = col & 127;
                *reinterpret_cast<uint32_t*>(hdst + ((size_t)ra * NH + head) * 128 + d) = packh2(d0, d1);
                *reinterpret_cast<uint32_t*>(hdst + ((size_t)rb * NH + head) * 128 + d) = packh2(d2, d3);
            } else {
                *reinterpret_cast<float2*>(&C[(size_t)ra * DIM + col]) = make_float2(d0, d1);
                *reinterpret_cast<float2*>(&C[(size_t)rb * DIM + col]) = make_float2(d2, d3);
            }
        }
    }
}

__global__ __launch_bounds__(128, 2) void qkv_gemm_kernel(const float* __restrict__ freqs)
{
    const int z = blockIdx.z;
    const __half* B = g_wh + (size_t)z * DIM * DIM;
    __half* dst = (z == 0) ? g_qs : (z == 1) ? g_ks : g_vs;
    const float qsc = (z == 0) ? 0.08838834764831845f : 1.0f;
    hgemm_body(g_x, B, nullptr, dst, 1, freqs, (z < 2) ? 1 : 0, qsc,
               blockIdx.x * 128, blockIdx.y * 128);
}

__global__ __launch_bounds__(128, 2) void out_gemm_kernel(float* __restrict__ out)
{
    hgemm_body(g_a, g_wh + 3ull * DIM * DIM, out, nullptr, 0, nullptr, 0, 1.0f,
               blockIdx.x * 128, blockIdx.y * 128);
}

// ---------------- fp16 flash attention: 64-q CTAs, Q in registers -----------
// CTA: 64 q x 64 kv, 4 warps (16 q rows each). q, K, V plain fp16.
#define KVS 136                       // smem row stride (128 + 8)
#define ATTN_SMEM ((64 * KVS + 4 * 64 * KVS) * (int)sizeof(__half))  // 87040

__global__ __launch_bounds__(128, 2) void attn_kernel()
{
    extern __shared__ __half sm_attn[];
    __half* sQ = sm_attn;                  // 64 x KVS (staging only)
    __half* sK = sQ + 64 * KVS;            // 2 x 64 x KVS
    __half* sV = sK + 2 * 64 * KVS;        // 2 x 64 x KVS

    const int h   = blockIdx.y;
    const int q0  = (gridDim.x - 1 - blockIdx.x) * 64;    // heavy tiles first
    const int tid = threadIdx.x;
    const int wid = tid >> 5, lane = tid & 31;

    // stage Q (own cp.async group)
    for (int i = tid; i < 64 * 16; i += 128) {
        int r = i >> 4, c = i & 15;
        cp_async16(smem_u32(sQ + r * KVS) + c * 16,
                   g_qs + ((size_t)(q0 + r) * NH + h) * 128 + c * 8);
    }
    CP_COMMIT();

    const int nt = q0 / 64 + 1;

    auto load_kv = [&](int t, int s) {
        for (int i = tid; i < 64 * 16 * 2; i += 128) {
            int half_sel = i >= 64 * 16;
            int j = i & (64 * 16 - 1);
            int r = j >> 4, c = j & 15;
            size_t src = ((size_t)(t * 64 + r) * NH + h) * 128 + c * 8;
            __half* dst = (half_sel ? sV : sK) + (s * 64 + r) * KVS + c * 8;
            cp_async16(smem_u32(dst), (half_sel ? g_vs : g_ks) + src);
        }
        CP_COMMIT();
    };
    load_kv(0, 0);

    // Q is ready when only kv(0) remains pending; hoist Q frags to registers.
    CP_WAIT(1);
    __syncthreads();
    uint32_t qf[8][4];
    {
        const uint32_t Qb = smem_u32(sQ);
        const uint32_t qrow_off = (uint32_t)((wid * 16 + (lane & 15)) * KVS + ((lane >> 4) << 3));
#pragma unroll
        for (int kk = 0; kk < 8; kk++)
            ldm_x4(qf[kk], Qb + (qrow_off + kk * 16) * 2);
    }

    float m0 = -1e30f, m1 = -1e30f, l0 = 0.0f, l1 = 0.0f;
    float O[16][4];
#pragma unroll
    for (int n = 0; n < 16; n++)
#pragma unroll
        for (int j = 0; j < 4; j++) O[n][j] = 0.0f;

    const int wrow = q0 + wid * 16;
    const int r0g  = wrow + (lane >> 2);
    const uint32_t krow = (uint32_t)(((lane >> 4) << 3) + (lane & 7));
    const uint32_t kcol = (uint32_t)(((lane >> 3) & 1) << 3);
    const uint32_t vrow_off = (uint32_t)(lane & 15);
    const uint32_t vcol8 = (uint32_t)((lane >> 4) << 3);

    for (int t = 0; t < nt; t++) {
        if (t + 1 < nt) { load_kv(t + 1, (t + 1) & 1); CP_WAIT(1); }
        else           { CP_WAIT(0); }
        __syncthreads();
        const int k0 = t * 64;

        {
            const uint32_t Kb = smem_u32(sK + (t & 1) * 64 * KVS);
            const uint32_t Vb = smem_u32(sV + (t & 1) * 64 * KVS);

            float s[8][4];
#pragma unroll
            for (int j = 0; j < 8; j++)
#pragma unroll
                for (int i = 0; i < 4; i++) s[j][i] = 0.0f;

            // ---- S = q . K  (Q from registers) ----
#pragma unroll
            for (int kk = 0; kk < 8; kk++) {
#pragma unroll
                for (int g = 0; g < 4; g++) {
                    uint32_t kb[4];
                    ldm_x4(kb, Kb + ((g * 16 + krow) * KVS + kcol + kk * 16) * 2);
                    mma16816h(s[2 * g],     qf[kk], kb[0], kb[1]);
                    mma16816h(s[2 * g + 1], qf[kk], kb[2], kb[3]);
                }
            }

            if (k0 + 63 > wrow) {
                const int c0 = k0 + ((lane & 3) << 1);
#pragma unroll
                for (int j = 0; j < 8; j++) {
                    int cc = c0 + j * 8;
                    if (cc     > r0g)     s[j][0] = -1e30f;
                    if (cc + 1 > r0g)     s[j][1] = -1e30f;
                    if (cc     > r0g + 8) s[j][2] = -1e30f;
                    if (cc + 1 > r0g + 8) s[j][3] = -1e30f;
                }
            }

            float mt0 = -1e30f, mt1 = -1e30f;
#pragma unroll
            for (int j = 0; j < 8; j++) {
                mt0 = fmaxf(mt0, fmaxf(s[j][0], s[j][1]));
                mt1 = fmaxf(mt1, fmaxf(s[j][2], s[j][3]));
            }
            mt0 = fmaxf(mt0, __shfl_xor_sync(0xffffffffu, mt0, 1));
            mt0 = fmaxf(mt0, __shfl_xor_sync(0xffffffffu, mt0, 2));
            mt1 = fmaxf(mt1, __shfl_xor_sync(0xffffffffu, mt1, 1));
            mt1 = fmaxf(mt1, __shfl_xor_sync(0xffffffffu, mt1, 2));
            const float mn0 = fmaxf(m0, mt0), mn1 = fmaxf(m1, mt1);
            const float corr0 = __expf(m0 - mn0), corr1 = __expf(m1 - mn1);
            m0 = mn0; m1 = mn1;
            float rs0 = 0.0f, rs1 = 0.0f;
#pragma unroll
            for (int j = 0; j < 8; j++) {
                s[j][0] = __expf(s[j][0] - mn0);
                s[j][1] = __expf(s[j][1] - mn0);
                s[j][2] = __expf(s[j][2] - mn1);
                s[j][3] = __expf(s[j][3] - mn1);
                rs0 += s[j][0] + s[j][1];
                rs1 += s[j][2] + s[j][3];
            }
            rs0 += __shfl_xor_sync(0xffffffffu, rs0, 1);
            rs0 += __shfl_xor_sync(0xffffffffu, rs0, 2);
            rs1 += __shfl_xor_sync(0xffffffffu, rs1, 1);
            rs1 += __shfl_xor_sync(0xffffffffu, rs1, 2);
            l0 = l0 * corr0 + rs0;
            l1 = l1 * corr1 + rs1;
#pragma unroll
            for (int n = 0; n < 16; n++) {
                O[n][0] *= corr0;  O[n][1] *= corr0;
                O[n][2] *= corr1;  O[n][3] *= corr1;
            }

            // ---- O += P . V ----
#pragma unroll
            for (int kt = 0; kt < 4; kt++) {
                uint32_t ph[4];
                ph[0] = packh2(s[2 * kt][0],     s[2 * kt][1]);
                ph[1] = packh2(s[2 * kt][2],     s[2 * kt][3]);
                ph[2] = packh2(s[2 * kt + 1][0], s[2 * kt + 1][1]);
                ph[3] = packh2(s[2 * kt + 1][2], s[2 * kt + 1][3]);
#pragma unroll
                for (int g = 0; g < 8; g++) {
                    uint32_t vb[4];
                    ldm_x4_t(vb, Vb + ((kt * 16 + vrow_off) * KVS + g * 16 + vcol8) * 2);
                    mma16816h(O[2 * g],     ph, vb[0], vb[1]);
                    mma16816h(O[2 * g + 1], ph, vb[2], vb[3]);
                }
            }
        }
        __syncthreads();
    }

    // ---- normalize + store fp16 to g_a ----
    const float inv0 = 1.0f / l0, inv1 = 1.0f / l1;
    const int sr0 = wrow + (lane >> 2), sr1 = sr0 + 8;
#pragma unroll
    for (int n = 0; n < 16; n++) {
        const int d = n * 8 + ((lane & 3) << 1);
        {
            float v0 = O[n][0] * inv0, v1 = O[n][1] * inv0;
            __half* p = g_a + (size_t)sr0 * DIM + h * 128 + d;
            *reinterpret_cast<uint32_t*>(p) = packh2(v0, v1);
        }
        {
            float v2 = O[n][2] * inv1, v3 = O[n][3] * inv1;
            __half* p = g_a + (size_t)sr1 * DIM + h * 128 + d;
            *reinterpret_cast<uint32_t*>(p) = packh2(v2, v3);
        }
    }
}

// ---------------- launch -----------------------------------------------------
// inputs: 0:x 1:start_pos 2:freqs 3:mask 4:wq 5:wk 6:wv 7:wo  (mask analytic)
extern "C" void kernel_launch(void* const* d_in, const int* in_sizes, int n_in,
                              void* d_out, int out_size)
{
    const float* x     = (const float*)d_in[0];
    const float* freqs = (const float*)d_in[2];
    const float* wq    = (const float*)d_in[4];
    const float* wk    = (const float*)d_in[5];
    const float* wv    = (const float*)d_in[6];
    const float* wo    = (const float*)d_in[7];
    float* out = (float*)d_out;

    cudaFuncSetAttribute(attn_kernel,     cudaFuncAttributeMaxDynamicSharedMemorySize, ATTN_SMEM);
    cudaFuncSetAttribute(qkv_gemm_kernel, cudaFuncAttributeMaxDynamicSharedMemorySize, GEMM_SMEM);
    cudaFuncSetAttribute(out_gemm_kernel, cudaFuncAttributeMaxDynamicSharedMemorySize, GEMM_SMEM);

    convert_w_kernel<<<dim3(DIM * DIM / 4 / 256, 1, 4), 256>>>(wq, wk, wv, wo);
    convert_x_kernel<<<SEQ * DIM / 4 / 256, 256>>>(x);
    qkv_gemm_kernel<<<dim3(SEQ / 128, DIM / 128, 3), 128, GEMM_SMEM>>>(freqs);
    attn_kernel<<<dim3(SEQ / 64, NH), 128, ATTN_SMEM>>>();
    out_gemm_kernel<<<dim3(SEQ / 128, DIM / 128, 1), 128, GEMM_SMEM>>>(out);
}

// round 17
// speedup vs baseline: 2.3405x; 1.0501x over previous
#include <cuda_runtime.h>
#include <cuda_fp16.h>
#include <math.h>
#include <stdint.h>

#define SEQ 2048
#define DIM 4096
#define NH  32
#define HD  128

// ---------------- scratch (__device__ globals; no cudaMalloc allowed) -------
__device__ __half g_wh[4ull * DIM * DIM];                // weights, fp16
__device__ __half g_x [(size_t)SEQ * DIM];               // x  (fp16)
__device__ __half g_a [(size_t)SEQ * DIM];               // attn out (fp16)
__device__ __half g_qs[(size_t)SEQ * NH * 128];          // q per head, fp16
__device__ __half g_ks[(size_t)SEQ * NH * 128];          // k per head, fp16
__device__ __half g_vs[(size_t)SEQ * NH * 128];          // v per head, fp16

// ---------------- PTX helpers ----------------------------------------------
__device__ __forceinline__ uint32_t smem_u32(const void* p) {
    uint32_t a;
    asm("{ .reg .u64 t; cvta.to.shared.u64 t, %1; cvt.u32.u64 %0, t; }" : "=r"(a) : "l"(p));
    return a;
}
__device__ __forceinline__ void cp_async16(uint32_t dst, const void* src) {
    asm volatile("cp.async.cg.shared.global [%0], [%1], 16;" :: "r"(dst), "l"(src));
}
#define CP_COMMIT()  asm volatile("cp.async.commit_group;" ::: "memory")
#define CP_WAIT(n)   asm volatile("cp.async.wait_group %0;" :: "n"(n) : "memory")

__device__ __forceinline__ void ldm_x4(uint32_t* r, uint32_t addr) {
    asm volatile("ldmatrix.sync.aligned.m8n8.x4.shared.b16 {%0,%1,%2,%3}, [%4];"
        : "=r"(r[0]), "=r"(r[1]), "=r"(r[2]), "=r"(r[3]) : "r"(addr));
}
__device__ __forceinline__ void ldm_x4_t(uint32_t* r, uint32_t addr) {
    asm volatile("ldmatrix.sync.aligned.m8n8.x4.trans.shared.b16 {%0,%1,%2,%3}, [%4];"
        : "=r"(r[0]), "=r"(r[1]), "=r"(r[2]), "=r"(r[3]) : "r"(addr));
}
// fp16 mma, fp32 accum
__device__ __forceinline__ void mma16816h(float* c, const uint32_t* a, uint32_t b0, uint32_t b1) {
    asm volatile(
        "mma.sync.aligned.m16n8k16.row.col.f32.f16.f16.f32 "
        "{%0,%1,%2,%3}, {%4,%5,%6,%7}, {%8,%9}, {%0,%1,%2,%3};"
        : "+f"(c[0]), "+f"(c[1]), "+f"(c[2]), "+f"(c[3])
        : "r"(a[0]), "r"(a[1]), "r"(a[2]), "r"(a[3]), "r"(b0), "r"(b1));
}
__device__ __forceinline__ uint32_t packh2(float lo, float hi) {
    __half2 h = __floats2half2_rn(lo, hi);
    return *reinterpret_cast<uint32_t*>(&h);
}

// ---------------- converters -------------------------------------------------
__global__ __launch_bounds__(256) void convert_w_kernel(
    const float* __restrict__ w0, const float* __restrict__ w1,
    const float* __restrict__ w2, const float* __restrict__ w3)
{
    const float* w = (blockIdx.z == 0) ? w0 : (blockIdx.z == 1) ? w1 :
                     (blockIdx.z == 2) ? w2 : w3;
    __half* dst = g_wh + (size_t)blockIdx.z * DIM * DIM;
    int idx = blockIdx.x * 256 + threadIdx.x;
    float4 v = reinterpret_cast<const float4*>(w)[idx];
    __half hi[4];
    hi[0] = __float2half_rn(v.x); hi[1] = __float2half_rn(v.y);
    hi[2] = __float2half_rn(v.z); hi[3] = __float2half_rn(v.w);
    *reinterpret_cast<uint2*>(dst + (size_t)idx * 4) = *reinterpret_cast<uint2*>(hi);
}

__global__ __launch_bounds__(256) void convert_x_kernel(const float* __restrict__ x)
{
    int idx = blockIdx.x * 256 + threadIdx.x;
    float4 v = reinterpret_cast<const float4*>(x)[idx];
    __half hi[4];
    hi[0] = __float2half_rn(v.x); hi[1] = __float2half_rn(v.y);
    hi[2] = __float2half_rn(v.z); hi[3] = __float2half_rn(v.w);
    *reinterpret_cast<uint2*>(g_x + (size_t)idx * 4) = *reinterpret_cast<uint2*>(hi);
}

// ---------------- HMMA fp16 GEMM: 4 warps, warp tile 64x64 (R16 body) -------
#define BK 32
#define NKSTEP (DIM / BK)    // 128
#define ASTR 40
#define GSTAGES 3
#define GEMM_SMEM (GSTAGES * 2 * 128 * ASTR * (int)sizeof(__half))  // 61440
#define NSLOTS 296           // 148 SMs x 2 CTAs

__device__ __forceinline__ void hgemm_body(
    const __half* __restrict__ A,
    const __half* __restrict__ B,
    float* __restrict__ C,                 // omode 0
    __half* __restrict__ hdst,             // omode 1: per-head fp16
    int omode,
    const float* __restrict__ freqs, int rope, float qsc,
    int m0, int n0)
{
    extern __shared__ __half gsm[];
    __half* sA = gsm;
    __half* sB = gsm + GSTAGES * 128 * ASTR;

    const int tid  = threadIdx.x;
    const int wid  = tid >> 5;
    const int lane = tid & 31;
    const int wm   = wid >> 1;
    const int wn   = wid & 1;

    // protect smem stage reuse across persistent-loop iterations
    __syncthreads();

    float acc[4][8][4];
#pragma unroll
    for (int mi = 0; mi < 4; mi++)
#pragma unroll
        for (int ni = 0; ni < 8; ni++)
#pragma unroll
            for (int j = 0; j < 4; j++) acc[mi][ni][j] = 0.0f;

    const __half* agp = A + (size_t)m0 * DIM;
    const __half* bgp = B + (size_t)n0 * DIM;

    auto load_tile = [&](int kstep, int s) {
        const size_t ka = (size_t)kstep * BK;
#pragma unroll
        for (int l = 0; l < 4; l++) {
            int i = tid + l * 128;
            int r = i >> 2, seg = i & 3;
            cp_async16(smem_u32(sA + (s * 128 + r) * ASTR + seg * 8), agp + (size_t)r * DIM + ka + seg * 8);
            cp_async16(smem_u32(sB + (s * 128 + r) * ASTR + seg * 8), bgp + (size_t)r * DIM + ka + seg * 8);
        }
        CP_COMMIT();
    };

    load_tile(0, 0);
    load_tile(1, 1);

    for (int k = 0; k < NKSTEP; k++) {
        if (k + 1 < NKSTEP) { CP_WAIT(1); } else { CP_WAIT(0); }
        __syncthreads();
        if (k + 2 < NKSTEP) load_tile(k + 2, (k + 2) % GSTAGES);

        const int s = k % GSTAGES;
#pragma unroll
        for (int kk = 0; kk < 2; kk++) {
            const int k0 = kk * 16;
            uint32_t af[4][4], bf[8][2];
#pragma unroll
            for (int mi = 0; mi < 4; mi++) {
                int row = wm * 64 + mi * 16 + (lane & 15);
                ldm_x4(af[mi], smem_u32(sA + (s * 128 + row) * ASTR + k0 + ((lane >> 4) << 3)));
            }
#pragma unroll
            for (int np = 0; np < 4; np++) {
                int rown = wn * 64 + np * 16 + ((lane >> 4) << 3) + (lane & 7);
                uint32_t b[4];
                ldm_x4(b, smem_u32(sB + (s * 128 + rown) * ASTR + k0 + (((lane >> 3) & 1) << 3)));
                bf[2 * np][0] = b[0];  bf[2 * np][1] = b[1];
                bf[2 * np + 1][0] = b[2];  bf[2 * np + 1][1] = b[3];
            }
#pragma unroll
            for (int mi = 0; mi < 4; mi++)
#pragma unroll
                for (int ni = 0; ni < 8; ni++)
                    mma16816h(acc[mi][ni], af[mi], bf[ni][0], bf[ni][1]);
        }
    }

#pragma unroll
    for (int mi = 0; mi < 4; mi++) {
        const int ra = m0 + wm * 64 + mi * 16 + (lane >> 2);
        const int rb = ra + 8;
#pragma unroll
        for (int ni = 0; ni < 8; ni++) {
            const int col = n0 + wn * 64 + ni * 8 + ((lane & 3) << 1);
            float d0 = acc[mi][ni][0], d1 = acc[mi][ni][1];
            float d2 = acc[mi][ni][2], d3 = acc[mi][ni][3];
            if (rope) {
                const int hd = col & (HD - 1);
                float ca = freqs[ra * HD + hd], sa = freqs[ra * HD + hd + 1];
                float cb = freqs[rb * HD + hd], sb = freqs[rb * HD + hd + 1];
                d0 *= (ca - sa) * qsc;  d1 *= (ca + sa) * qsc;
                d2 *= (cb - sb) * qsc;  d3 *= (cb + sb) * qsc;
            }
            if (omode == 1) {
                const int head = col >> 7, d = col & 127;
                *reinterpret_cast<uint32_t*>(hdst + ((size_t)ra * NH + head) * 128 + d) = packh2(d0, d1);
                *reinterpret_cast<uint32_t*>(hdst + ((size_t)rb * NH + head) * 128 + d) = packh2(d2, d3);
            } else {
                *reinterpret_cast<float2*>(&C[(size_t)ra * DIM + col]) = make_float2(d0, d1);
                *reinterpret_cast<float2*>(&C[(size_t)rb * DIM + col]) = make_float2(d2, d3);
            }
        }
    }
}

// Persistent QKV: 1536 tiles (3 mats x 16 m x 32 n) over NSLOTS CTAs.
__global__ __launch_bounds__(128, 2) void qkv_gemm_kernel(const float* __restrict__ freqs)
{
    for (int t = blockIdx.x; t < 3 * 16 * 32; t += gridDim.x) {
        const int z  = t >> 9;           // /512
        const int r  = t & 511;
        const int mi = r >> 5;
        const int ni = r & 31;
        const __half* B = g_wh + (size_t)z * DIM * DIM;
        __half* dst = (z == 0) ? g_qs : (z == 1) ? g_ks : g_vs;
        const float qsc = (z == 0) ? 0.08838834764831845f : 1.0f;
        hgemm_body(g_x, B, nullptr, dst, 1, freqs, (z < 2) ? 1 : 0, qsc,
                   mi * 128, ni * 128);
    }
}

// Persistent out-proj: 512 tiles (16 m x 32 n) over NSLOTS CTAs.
__global__ __launch_bounds__(128, 2) void out_gemm_kernel(float* __restrict__ out)
{
    for (int t = blockIdx.x; t < 16 * 32; t += gridDim.x) {
        const int mi = t >> 5;
        const int ni = t & 31;
        hgemm_body(g_a, g_wh + 3ull * DIM * DIM, out, nullptr, 0, nullptr, 0, 1.0f,
                   mi * 128, ni * 128);
    }
}

// ---------------- fp16 flash attention: 64-q CTAs, Q in registers (R16) -----
#define KVS 136                       // smem row stride (128 + 8)
#define ATTN_SMEM ((64 * KVS + 4 * 64 * KVS) * (int)sizeof(__half))  // 87040

__global__ __launch_bounds__(128, 2) void attn_kernel()
{
    extern __shared__ __half sm_attn[];
    __half* sQ = sm_attn;                  // 64 x KVS (staging only)
    __half* sK = sQ + 64 * KVS;            // 2 x 64 x KVS
    __half* sV = sK + 2 * 64 * KVS;        // 2 x 64 x KVS

    const int h   = blockIdx.y;
    const int q0  = (gridDim.x - 1 - blockIdx.x) * 64;    // heavy tiles first
    const int tid = threadIdx.x;
    const int wid = tid >> 5, lane = tid & 31;

    for (int i = tid; i < 64 * 16; i += 128) {
        int r = i >> 4, c = i & 15;
        cp_async16(smem_u32(sQ + r * KVS) + c * 16,
                   g_qs + ((size_t)(q0 + r) * NH + h) * 128 + c * 8);
    }
    CP_COMMIT();

    const int nt = q0 / 64 + 1;

    auto load_kv = [&](int t, int s) {
        for (int i = tid; i < 64 * 16 * 2; i += 128) {
            int half_sel = i >= 64 * 16;
            int j = i & (64 * 16 - 1);
            int r = j >> 4, c = j & 15;
            size_t src = ((size_t)(t * 64 + r) * NH + h) * 128 + c * 8;
            __half* dst = (half_sel ? sV : sK) + (s * 64 + r) * KVS + c * 8;
            cp_async16(smem_u32(dst), (half_sel ? g_vs : g_ks) + src);
        }
        CP_COMMIT();
    };
    load_kv(0, 0);

    CP_WAIT(1);
    __syncthreads();
    uint32_t qf[8][4];
    {
        const uint32_t Qb = smem_u32(sQ);
        const uint32_t qrow_off = (uint32_t)((wid * 16 + (lane & 15)) * KVS + ((lane >> 4) << 3));
#pragma unroll
        for (int kk = 0; kk < 8; kk++)
            ldm_x4(qf[kk], Qb + (qrow_off + kk * 16) * 2);
    }

    float m0 = -1e30f, m1 = -1e30f, l0 = 0.0f, l1 = 0.0f;
    float O[16][4];
#pragma unroll
    for (int n = 0; n < 16; n++)
#pragma unroll
        for (int j = 0; j < 4; j++) O[n][j] = 0.0f;

    const int wrow = q0 + wid * 16;
    const int r0g  = wrow + (lane >> 2);
    const uint32_t krow = (uint32_t)(((lane >> 4) << 3) + (lane & 7));
    const uint32_t kcol = (uint32_t)(((lane >> 3) & 1) << 3);
    const uint32_t vrow_off = (uint32_t)(lane & 15);
    const uint32_t vcol8 = (uint32_t)((lane >> 4) << 3);

    for (int t = 0; t < nt; t++) {
        if (t + 1 < nt) { load_kv(t + 1, (t + 1) & 1); CP_WAIT(1); }
        else           { CP_WAIT(0); }
        __syncthreads();
        const int k0 = t * 64;

        {
            const uint32_t Kb = smem_u32(sK + (t & 1) * 64 * KVS);
            const uint32_t Vb = smem_u32(sV + (t & 1) * 64 * KVS);

            float s[8][4];
#pragma unroll
            for (int j = 0; j < 8; j++)
#pragma unroll
                for (int i = 0; i < 4; i++) s[j][i] = 0.0f;

#pragma unroll
            for (int kk = 0; kk < 8; kk++) {
#pragma unroll
                for (int g = 0; g < 4; g++) {
                    uint32_t kb[4];
                    ldm_x4(kb, Kb + ((g * 16 + krow) * KVS + kcol + kk * 16) * 2);
                    mma16816h(s[2 * g],     qf[kk], kb[0], kb[1]);
                    mma16816h(s[2 * g + 1], qf[kk], kb[2], kb[3]);
                }
            }

            if (k0 + 63 > wrow) {
                const int c0 = k0 + ((lane & 3) << 1);
#pragma unroll
                for (int j = 0; j < 8; j++) {
                    int cc = c0 + j * 8;
                    if (cc     > r0g)     s[j][0] = -1e30f;
                    if (cc + 1 > r0g)     s[j][1] = -1e30f;
                    if (cc     > r0g + 8) s[j][2] = -1e30f;
                    if (cc + 1 > r0g + 8) s[j][3] = -1e30f;
                }
            }

            float mt0 = -1e30f, mt1 = -1e30f;
#pragma unroll
            for (int j = 0; j < 8; j++) {
                mt0 = fmaxf(mt0, fmaxf(s[j][0], s[j][1]));
                mt1 = fmaxf(mt1, fmaxf(s[j][2], s[j][3]));
            }
            mt0 = fmaxf(mt0, __shfl_xor_sync(0xffffffffu, mt0, 1));
            mt0 = fmaxf(mt0, __shfl_xor_sync(0xffffffffu, mt0, 2));
            mt1 = fmaxf(mt1, __shfl_xor_sync(0xffffffffu, mt1, 1));
            mt1 = fmaxf(mt1, __shfl_xor_sync(0xffffffffu, mt1, 2));
            const float mn0 = fmaxf(m0, mt0), mn1 = fmaxf(m1, mt1);
            const float corr0 = __expf(m0 - mn0), corr1 = __expf(m1 - mn1);
            m0 = mn0; m1 = mn1;
            float rs0 = 0.0f, rs1 = 0.0f;
#pragma unroll
            for (int j = 0; j < 8; j++) {
                s[j][0] = __expf(s[j][0] - mn0);
                s[j][1] = __expf(s[j][1] - mn0);
                s[j][2] = __expf(s[j][2] - mn1);
                s[j][3] = __expf(s[j][3] - mn1);
                rs0 += s[j][0] + s[j][1];
                rs1 += s[j][2] + s[j][3];
            }
            rs0 += __shfl_xor_sync(0xffffffffu, rs0, 1);
            rs0 += __shfl_xor_sync(0xffffffffu, rs0, 2);
            rs1 += __shfl_xor_sync(0xffffffffu, rs1, 1);
            rs1 += __shfl_xor_sync(0xffffffffu, rs1, 2);
            l0 = l0 * corr0 + rs0;
            l1 = l1 * corr1 + rs1;
#pragma unroll
            for (int n = 0; n < 16; n++) {
                O[n][0] *= corr0;  O[n][1] *= corr0;
                O[n][2] *= corr1;  O[n][3] *= corr1;
            }

#pragma unroll
            for (int kt = 0; kt < 4; kt++) {
                uint32_t ph[4];
                ph[0] = packh2(s[2 * kt][0],     s[2 * kt][1]);
                ph[1] = packh2(s[2 * kt][2],     s[2 * kt][3]);
                ph[2] = packh2(s[2 * kt + 1][0], s[2 * kt + 1][1]);
                ph[3] = packh2(s[2 * kt + 1][2], s[2 * kt + 1][3]);
#pragma unroll
                for (int g = 0; g < 8; g++) {
                    uint32_t vb[4];
                    ldm_x4_t(vb, Vb + ((kt * 16 + vrow_off) * KVS + g * 16 + vcol8) * 2);
                    mma16816h(O[2 * g],     ph, vb[0], vb[1]);
                    mma16816h(O[2 * g + 1], ph, vb[2], vb[3]);
                }
            }
        }
        __syncthreads();
    }

    const float inv0 = 1.0f / l0, inv1 = 1.0f / l1;
    const int sr0 = wrow + (lane >> 2), sr1 = sr0 + 8;
#pragma unroll
    for (int n = 0; n < 16; n++) {
        const int d = n * 8 + ((lane & 3) << 1);
        {
            float v0 = O[n][0] * inv0, v1 = O[n][1] * inv0;
            __half* p = g_a + (size_t)sr0 * DIM + h * 128 + d;
            *reinterpret_cast<uint32_t*>(p) = packh2(v0, v1);
        }
        {
            float v2 = O[n][2] * inv1, v3 = O[n][3] * inv1;
            __half* p = g_a + (size_t)sr1 * DIM + h * 128 + d;
            *reinterpret_cast<uint32_t*>(p) = packh2(v2, v3);
        }
    }
}

// ---------------- launch -----------------------------------------------------
// inputs: 0:x 1:start_pos 2:freqs 3:mask 4:wq 5:wk 6:wv 7:wo  (mask analytic)
extern "C" void kernel_launch(void* const* d_in, const int* in_sizes, int n_in,
                              void* d_out, int out_size)
{
    const float* x     = (const float*)d_in[0];
    const float* freqs = (const float*)d_in[2];
    const float* wq    = (const float*)d_in[4];
    const float* wk    = (const float*)d_in[5];
    const float* wv    = (const float*)d_in[6];
    const float* wo    = (const float*)d_in[7];
    float* out = (float*)d_out;

    cudaFuncSetAttribute(attn_kernel,     cudaFuncAttributeMaxDynamicSharedMemorySize, ATTN_SMEM);
    cudaFuncSetAttribute(qkv_gemm_kernel, cudaFuncAttributeMaxDynamicSharedMemorySize, GEMM_SMEM);
    cudaFuncSetAttribute(out_gemm_kernel, cudaFuncAttributeMaxDynamicSharedMemorySize, GEMM_SMEM);

    convert_w_kernel<<<dim3(DIM * DIM / 4 / 256, 1, 4), 256>>>(wq, wk, wv, wo);
    convert_x_kernel<<<SEQ * DIM / 4 / 256, 256>>>(x);
    qkv_gemm_kernel<<<NSLOTS, 128, GEMM_SMEM>>>(freqs);
    attn_kernel<<<dim3(SEQ / 64, NH), 128, ATTN_SMEM>>>();
    out_gemm_kernel<<<NSLOTS, 128, GEMM_SMEM>>>(out);
}